// round 5
// baseline (speedup 1.0000x reference)
#include <cuda_runtime.h>
#include <cstdint>
#include <math.h>

typedef unsigned long long u64;
typedef unsigned int u32;

#define K_PRE 6000
#define K_POST 300
#define NMS_TH 0.7f
#define NROW 6016
#define NWORD 94
#define WSTRIDE 96
#define MAXB 2
#define CAP 16384
#define SPEC_W 32
#define SPEC_RT 8
#define RC_COLS 1024

// ---------- persistent device scratch (self-cleaning across graph replays) ----------
__device__ int    g_hist[MAXB * 65536];     // zeroed by k_thresh after reading
__device__ u32    g_T16[MAXB];
__device__ int    g_ccount[MAXB];           // zeroed by k_out
__device__ u32    g_chi[MAXB * CAP];        // candidate key hi (score map)
__device__ u32    g_clo[MAXB * CAP];        // candidate key lo (~index)
__device__ u32    g_rank[MAXB * CAP];       // gt | (eq<<16); zeroed by k_thresh
__device__ float4 g_box[2 * MAXB * NROW];
__device__ float  g_area[2 * MAXB * NROW];
__device__ u64    g_mask[(size_t)2 * MAXB * NROW * WSTRIDE];
__device__ u64    g_keep[2 * MAXB * NWORD];
__device__ int    g_prog[MAXB];
__device__ int    g_comb[MAXB];
__device__ int    g_full;                   // fallback flag, reset by k_out

__device__ __forceinline__ u32 score_map(float s) {
    u32 u = __float_as_uint(s);
    return (u & 0x80000000u) ? ~u : (u | 0x80000000u);
}

// ---------- 1: histogram of 16-bit score prefixes ----------
__global__ void k_hist(const float* __restrict__ scores, int B, int N) {
    int idx = blockIdx.x * blockDim.x + threadIdx.x;
    if (idx >= B * N) return;
    int b = idx / N;
    u32 u = score_map(scores[(size_t)idx * 2 + 1]);
    atomicAdd(&g_hist[(b << 16) + (int)(u >> 16)], 1);
}

// ---------- 2: threshold bin (shared-memory scans); self-clean hist + rank ----------
__global__ void k_thresh(void) {
    int b = blockIdx.x;
    int t = threadIdx.x;                  // 256
    __shared__ int part[256];
    __shared__ int sbin[256];
    __shared__ int s_seg, s_cum;
    int* h = &g_hist[b << 16];
    const int4* h4 = (const int4*)(h + t * 256);
    int sum = 0;
#pragma unroll 8
    for (int k = 0; k < 64; k++) {
        int4 v = h4[k];
        sum += v.x + v.y + v.z + v.w;
    }
    part[t] = sum;
    __syncthreads();
    if (t == 0) {
        int cum = 0, seg = 255;
        for (; seg > 0; seg--) {
            if (cum + part[seg] >= K_PRE) break;
            cum += part[seg];
        }
        s_seg = seg; s_cum = cum;
    }
    __syncthreads();
    sbin[t] = h[s_seg * 256 + t];
    __syncthreads();
    if (t == 0) {
        int cum = s_cum, bin = 255;
        for (;; bin--) {
            int c = sbin[bin];
            if (cum + c >= K_PRE || bin == 0) break;
            cum += c;
        }
        g_T16[b] = (u32)(s_seg * 256 + bin);
    }
    // self-clean for next replay
    int4* hz = (int4*)(h + t * 256);
    int4 z = make_int4(0, 0, 0, 0);
#pragma unroll 8
    for (int k = 0; k < 64; k++) hz[k] = z;
    uint4* rz = (uint4*)&g_rank[b * CAP];
    uint4 uz = make_uint4(0, 0, 0, 0);
    for (int k = t; k < CAP / 4; k += 256) rz[k] = uz;
}

// ---------- 3: compact candidates with prefix16 >= threshold ----------
__global__ void k_compact(const float* __restrict__ scores, int B, int N) {
    int idx = blockIdx.x * blockDim.x + threadIdx.x;
    if (idx >= B * N) return;
    int b = idx / N;
    int i = idx - b * N;
    u32 u = score_map(scores[(size_t)idx * 2 + 1]);
    if ((u >> 16) >= g_T16[b]) {
        int p = atomicAdd(&g_ccount[b], 1);
        if (p < CAP) {
            g_chi[b * CAP + p] = u;
            g_clo[b * CAP + p] = 0xFFFFFFFFu - (u32)i;
        }
    }
}

// ---------- 4: parallel rank counting on hi words (vectorized) ----------
__global__ void k_rankcnt(void) {
    int b = blockIdx.z;
    int C = g_ccount[b];
    if (C > CAP) C = CAP;
    int j0 = blockIdx.x * 256;
    int c0 = blockIdx.y * RC_COLS;
    if (j0 >= C || c0 >= C) return;        // uniform per block
    __shared__ u32 tile[RC_COLS];
    int j = j0 + threadIdx.x;
    u32 my = (j < C) ? g_chi[b * CAP + j] : 0xFFFFFFFFu;
    int nt = min(RC_COLS, C - c0);
    // pad to multiple of 4 with 0 (0 < any candidate hi, which has top bit set)
    int ntp = (nt + 3) & ~3;
    for (int t = threadIdx.x; t < ntp; t += 256)
        tile[t] = (t < nt) ? g_chi[b * CAP + c0 + t] : 0u;
    __syncthreads();
    u32 gt = 0, eq = 0;
    const uint4* t4 = (const uint4*)tile;
    int n4 = ntp >> 2;
#pragma unroll 4
    for (int k = 0; k < n4; k++) {
        uint4 v = t4[k];
        gt += (v.x > my); eq += (v.x == my);
        gt += (v.y > my); eq += (v.y == my);
        gt += (v.z > my); eq += (v.z == my);
        gt += (v.w > my); eq += (v.w == my);
    }
    if (j < C) atomicAdd(&g_rank[b * CAP + j], gt | (eq << 16));
}

// ---------- 5: gather + decode + clip by final rank (exact tie resolution) ----------
__global__ void k_gather(const float* __restrict__ deltas, const float* __restrict__ iminfo,
                         const float* __restrict__ anchors, int B, int N) {
    int b = blockIdx.y;
    int C = g_ccount[b];
    if (C > CAP) C = CAP;
    if ((int)blockIdx.x * 256 >= C) return;
    int j = blockIdx.x * 256 + threadIdx.x;
    if (j >= C) return;
    u32 val = g_rank[b * CAP + j];
    int rank = (int)(val & 0xFFFFu);
    int eq = (int)(val >> 16);               // includes self
    u32 my_hi = g_chi[b * CAP + j];
    u32 my_lo = g_clo[b * CAP + j];
    if (eq > 1) {                            // rare: same mapped score, order by lo desc
        for (int t = 0; t < C; t++)
            if (g_chi[b * CAP + t] == my_hi && g_clo[b * CAP + t] > my_lo) rank++;
    }
    if (rank >= K_PRE) return;
    int i = (int)(0xFFFFFFFFu - my_lo);

    const float* a = anchors + (size_t)i * 4;
    float w = a[2] - a[0] + 1.0f;
    float h = a[3] - a[1] + 1.0f;
    float cx = a[0] + 0.5f * w;
    float cy = a[1] + 0.5f * h;
    const float* d = deltas + ((size_t)b * N + i) * 6;
    float d0 = d[0], d1 = d[1], d2 = d[2], d3 = d[3], d4 = d[4], d5 = d[5];
    float Hm1 = iminfo[b * 3 + 0] - 1.0f;
    float Wm1 = iminfo[b * 3 + 1] - 1.0f;
    float eh = (float)exp((double)d3) * h;   // accurate exp (fast-math safe)
    float pcy = d1 * h + cy;
    float y1 = fminf(fmaxf(pcy - 0.5f * eh, 0.f), Hm1);
    float y2 = fminf(fmaxf(pcy + 0.5f * eh, 0.f), Hm1);
    {
        float pcx = d0 * w + cx;
        float pw = (float)exp((double)d2) * w;
        float x1 = fminf(fmaxf(pcx - 0.5f * pw, 0.f), Wm1);
        float x2 = fminf(fmaxf(pcx + 0.5f * pw, 0.f), Wm1);
        g_box[(b * 2 + 0) * NROW + rank] = make_float4(x1, y1, x2, y2);
        g_area[(b * 2 + 0) * NROW + rank] = (x2 - x1 + 1.0f) * (y2 - y1 + 1.0f);
    }
    {
        float pcx = d4 * w + cx;
        float pw = (float)exp((double)d5) * w;
        float x1 = fminf(fmaxf(pcx - 0.5f * pw, 0.f), Wm1);
        float x2 = fminf(fmaxf(pcx + 0.5f * pw, 0.f), Wm1);
        g_box[(b * 2 + 1) * NROW + rank] = make_float4(x1, y1, x2, y2);
        g_area[(b * 2 + 1) * NROW + rank] = (x2 - x1 + 1.0f) * (y2 - y1 + 1.0f);
    }
}

// ---------- IoU mask tile: 256 rows x 64 cols ----------
struct TileSh { float x1[64], y1[64], x2[64], y2[64], ar[64]; };

__device__ __forceinline__ void do_tile(TileSh* sh, int bset, int rt, int cc) {
    int t = threadIdx.x;         // 256
    int jg0 = cc * 64;
    if (t < 64) {
        float4 bj = g_box[bset * NROW + jg0 + t];
        sh->x1[t] = bj.x; sh->y1[t] = bj.y; sh->x2[t] = bj.z; sh->y2[t] = bj.w;
        sh->ar[t] = g_area[bset * NROW + jg0 + t];
    }
    __syncthreads();
    int i = rt * 256 + t;
    if (i < NROW) {
        float4 bi = g_box[bset * NROW + i];
        float ai = g_area[bset * NROW + i];
        u64 word = 0;
#pragma unroll 4
        for (int k = 0; k < 64; k++) {
            float xx1 = fmaxf(bi.x, sh->x1[k]);
            float yy1 = fmaxf(bi.y, sh->y1[k]);
            float xx2 = fminf(bi.z, sh->x2[k]);
            float yy2 = fminf(bi.w, sh->y2[k]);
            float ow = xx2 - xx1 + 1.0f;
            float oh = yy2 - yy1 + 1.0f;
            bool sup = false;
            if (ow > 0.0f && oh > 0.0f && (jg0 + k) > i) {
                float inter = ow * oh;
                float uni = ai + sh->ar[k] - inter;
                float p = NMS_TH * uni;
                sup = inter > p;
                if (fabsf(inter - p) <= 1e-5f * uni)            // borderline: exact IEEE decision
                    sup = __fdiv_rn(inter, uni) > NMS_TH;
            }
            if (sup) word |= 1ull << k;
        }
        g_mask[((size_t)bset * NROW + i) * WSTRIDE + cc] = word;
    }
    __syncthreads();
}

// ---------- 6: speculative mask (first 2048 rows/cols) ----------
__global__ void k_mask_spec(void) {
    __shared__ TileSh sh;
    int cc = blockIdx.x;
    int rt = blockIdx.y;
    if (cc < rt * 4) return;
    do_tile(&sh, blockIdx.z, rt, cc);
}

// ---------- 8: fallback full mask (flag-guarded, skips spec region) ----------
__global__ void k_mask_full(int B) {
    if (!g_full) return;
    __shared__ TileSh sh;
    const int PER_SET = 1008;
    int total = PER_SET * 2 * B;
    for (int tix = blockIdx.x; tix < total; tix += gridDim.x) {
        int set = tix / PER_SET;
        int r = tix - set * PER_SET;
        int rt, cc;
        if (r < 496) {
            rt = r / 62;
            cc = 32 + (r - rt * 62);
        } else {
            r -= 496;
            rt = 8;
            int cnt = 94 - 4 * 8;
            while (r >= cnt) { r -= cnt; rt++; cnt = 94 - 4 * rt; }
            cc = 4 * rt + r;
        }
        do_tile(&sh, set, rt, cc);
    }
}

// ---------- greedy NMS scan (shared by spec/full) ----------
__device__ __forceinline__ void scan_body(int b, int limit, int spec) {
    __shared__ u64 sh_keep[2][NWORD];
    __shared__ u64 sh_diag[2][64];
    __shared__ u64 sh_next[2], sh_cur[2];
    __shared__ int sh_comb, sh_done;
    int t = threadIdx.x;          // 128
    int set = t >> 6;
    int lt = t & 63;
    const u64* M = &g_mask[(size_t)(b * 2 + set) * NROW * WSTRIDE];
    if (t == 0) { sh_comb = 0; sh_done = 0; sh_cur[0] = 0; sh_cur[1] = 0; }
    __syncthreads();
    int c = 0;
    for (; c < limit; c++) {
        if (t < 2) sh_next[t] = 0;
        sh_diag[set][lt] = M[(size_t)(c * 64 + lt) * WSTRIDE + c];
        __syncthreads();
        if (lt == 0) {
            u64 cur = sh_cur[set];
            u64 keep = 0;
            int lim = min(64, K_PRE - c * 64);
            for (int k = 0; k < lim; k++) {
                if (!((cur >> k) & 1ull)) { keep |= 1ull << k; cur |= sh_diag[set][k]; }
            }
            sh_keep[set][c] = keep;
            g_keep[(b * 2 + set) * NWORD + c] = keep;
        }
        __syncthreads();
        if (t == 0) {
            sh_comb += __popcll(sh_keep[0][c] & sh_keep[1][c]);
            if (sh_comb >= K_POST) sh_done = 1;
        }
        __syncthreads();
        if (sh_done) { c++; break; }
        if (c + 1 < limit) {
            u64 acc = 0;
            for (int r = lt; r < (c + 1) * 64; r += 64) {
                u64 kw = sh_keep[set][r >> 6];
                if ((kw >> (r & 63)) & 1ull) acc |= M[(size_t)r * WSTRIDE + (c + 1)];
            }
            for (int o = 16; o; o >>= 1) acc |= __shfl_xor_sync(0xffffffffu, acc, o);
            if ((t & 31) == 0) atomicOr(&sh_next[set], acc);
            __syncthreads();
            if (lt == 0) sh_cur[set] = sh_next[set];
        }
    }
    if (t == 0) {
        if (spec && !sh_done) {
            g_full = 1;
        } else {
            g_prog[b] = c;
            g_comb[b] = sh_comb;
        }
    }
}

__global__ void k_scan_spec(void) { scan_body(blockIdx.x, SPEC_W, 1); }
__global__ void k_scan_full(void) { if (g_full) scan_body(blockIdx.x, NWORD, 0); }

// ---------- 10: emit outputs + self-clean counters ----------
__global__ void k_out(float* __restrict__ out, int B) {
    int b = blockIdx.x;
    int t = threadIdx.x;          // 128
    __shared__ int pref[NWORD];
    __shared__ u64 comb[NWORD];
    int chunks = g_prog[b];
    int nk = g_comb[b];
    if (nk > K_POST) nk = K_POST;
    float* outL = out + (size_t)b * K_POST * 5;
    float* outR = out + (size_t)(B + b) * K_POST * 5;
    for (int i = t; i < K_POST * 5; i += 128) {
        float v = (i % 5 == 0) ? (float)b : 0.f;
        outL[i] = v;
        outR[i] = v;
    }
    for (int w = t; w < NWORD; w += 128)
        comb[w] = (w < chunks) ? (g_keep[(b * 2) * NWORD + w] & g_keep[(b * 2 + 1) * NWORD + w]) : 0ull;
    __syncthreads();
    if (t == 0) {
        int s = 0;
        for (int w = 0; w < NWORD; w++) { pref[w] = s; s += __popcll(comb[w]); }
        g_ccount[b] = 0;
        if (b == 0) g_full = 0;
    }
    __syncthreads();
    for (int w = t; w < NWORD; w += 128) {
        int rank = pref[w];
        u64 m = comb[w];
        while (m && rank < nk) {
            int k = __ffsll((long long)m) - 1;
            m &= m - 1;
            int r = w * 64 + k;
            float4 bl = g_box[(b * 2 + 0) * NROW + r];
            float4 br = g_box[(b * 2 + 1) * NROW + r];
            outL[rank * 5 + 1] = bl.x; outL[rank * 5 + 2] = bl.y;
            outL[rank * 5 + 3] = bl.z; outL[rank * 5 + 4] = bl.w;
            outR[rank * 5 + 1] = br.x; outR[rank * 5 + 2] = br.y;
            outR[rank * 5 + 3] = br.z; outR[rank * 5 + 4] = br.w;
            rank++;
        }
    }
}

extern "C" void kernel_launch(void* const* d_in, const int* in_sizes, int n_in,
                              void* d_out, int out_size) {
    const float* scores  = (const float*)d_in[0];
    const float* deltas  = (const float*)d_in[1];
    const float* iminfo  = (const float*)d_in[2];
    const float* anchors = (const float*)d_in[3];
    float* out = (float*)d_out;
    int B = in_sizes[2] / 3;
    int N = in_sizes[3] / 4;
    int bn = B * N;
    int g = (bn + 255) / 256;

    k_hist<<<g, 256>>>(scores, B, N);
    k_thresh<<<B, 256>>>();
    k_compact<<<g, 256>>>(scores, B, N);
    k_rankcnt<<<dim3(CAP / 256, CAP / RC_COLS, B), 256>>>();
    k_gather<<<dim3(CAP / 256, B), 256>>>(deltas, iminfo, anchors, B, N);
    k_mask_spec<<<dim3(SPEC_W, SPEC_RT, 2 * B), 256>>>();
    k_scan_spec<<<B, 128>>>();
    k_mask_full<<<296, 256>>>(B);     // no-op unless g_full set
    k_scan_full<<<B, 128>>>();        // no-op unless g_full set
    k_out<<<B, 128>>>(out, B);
}

// round 7
// speedup vs baseline: 2.0318x; 2.0318x over previous
#include <cuda_runtime.h>
#include <cstdint>
#include <math.h>

typedef unsigned long long u64;
typedef unsigned int u32;

#define K_PRE 6000
#define K_SPEC 2048
#define K_POST 300
#define NMS_TH 0.7f
#define NROW 6016
#define NWORD 94
#define WSTRIDE 96
#define MAXB 2
#define CAP 16384
#define SCAP 4096
#define SPEC_W 32
#define SPEC_RT 8
#define FB_TILE 2048

// ---------- persistent device scratch (self-cleaning across graph replays) ----------
__device__ int    g_hist[MAXB * 65536];     // zeroed by k_hist last block
__device__ u32    g_done;                    // zeroed by k_hist last block
__device__ u32    g_T16[MAXB], g_T16s[MAXB];
__device__ int    g_ccount[MAXB], g_scount[MAXB];   // zeroed by k_fallback (always)
__device__ u64    g_cand[MAXB * CAP];
__device__ u64    g_scand[MAXB * SCAP];
__device__ float4 g_box[2 * MAXB * NROW];
__device__ float  g_area[2 * MAXB * NROW];
__device__ u64    g_mask[(size_t)2 * MAXB * NROW * WSTRIDE];
__device__ int    g_full;                    // reset by k_fallback

__device__ __forceinline__ u32 score_map(float s) {
    u32 u = __float_as_uint(s);
    return (u & 0x80000000u) ? ~u : (u | 0x80000000u);
}

__device__ __forceinline__ bool iou_sup(float4 bi, float ai,
                                        float x1, float y1, float x2, float y2, float ar) {
    float xx1 = fmaxf(bi.x, x1), yy1 = fmaxf(bi.y, y1);
    float xx2 = fminf(bi.z, x2), yy2 = fminf(bi.w, y2);
    float ow = xx2 - xx1 + 1.0f, oh = yy2 - yy1 + 1.0f;
    if (!(ow > 0.0f && oh > 0.0f)) return false;
    float inter = ow * oh;
    float uni = ai + ar - inter;
    float p = NMS_TH * uni;
    bool sup = inter > p;
    if (fabsf(inter - p) <= 1e-5f * uni)     // borderline: exact IEEE decision
        sup = __fdiv_rn(inter, uni) > NMS_TH;
    return sup;
}

__device__ __forceinline__ void decode_write(int b, int rank, u32 lo,
        const float* __restrict__ deltas, const float* __restrict__ iminfo,
        const float* __restrict__ anchors, int N) {
    int i = (int)(0xFFFFFFFFu - lo);
    const float* a = anchors + (size_t)i * 4;
    float w = a[2] - a[0] + 1.0f;
    float h = a[3] - a[1] + 1.0f;
    float cx = a[0] + 0.5f * w;
    float cy = a[1] + 0.5f * h;
    const float* d = deltas + ((size_t)b * N + i) * 6;
    float Hm1 = iminfo[b * 3 + 0] - 1.0f;
    float Wm1 = iminfo[b * 3 + 1] - 1.0f;
    float eh = (float)exp((double)d[3]) * h;   // accurate exp (fast-math safe)
    float pcy = d[1] * h + cy;
    float y1 = fminf(fmaxf(pcy - 0.5f * eh, 0.f), Hm1);
    float y2 = fminf(fmaxf(pcy + 0.5f * eh, 0.f), Hm1);
    {
        float pcx = d[0] * w + cx;
        float pw = (float)exp((double)d[2]) * w;
        float x1 = fminf(fmaxf(pcx - 0.5f * pw, 0.f), Wm1);
        float x2 = fminf(fmaxf(pcx + 0.5f * pw, 0.f), Wm1);
        g_box[(b * 2 + 0) * NROW + rank] = make_float4(x1, y1, x2, y2);
        g_area[(b * 2 + 0) * NROW + rank] = (x2 - x1 + 1.0f) * (y2 - y1 + 1.0f);
    }
    {
        float pcx = d[4] * w + cx;
        float pw = (float)exp((double)d[5]) * w;
        float x1 = fminf(fmaxf(pcx - 0.5f * pw, 0.f), Wm1);
        float x2 = fminf(fmaxf(pcx + 0.5f * pw, 0.f), Wm1);
        g_box[(b * 2 + 1) * NROW + rank] = make_float4(x1, y1, x2, y2);
        g_area[(b * 2 + 1) * NROW + rank] = (x2 - x1 + 1.0f) * (y2 - y1 + 1.0f);
    }
}

// ---------- 1: histogram + (last block) both thresholds + self-clean ----------
__global__ void k_hist(const float* __restrict__ scores, int B, int N) {
    int idx = blockIdx.x * blockDim.x + threadIdx.x;
    int t = threadIdx.x;
    if (idx < B * N) {
        int b = idx / N;
        float2 sp = ((const float2*)scores)[idx];
        u32 u = score_map(sp.y);
        atomicAdd(&g_hist[(b << 16) + (int)(u >> 16)], 1);
    }
    __threadfence();
    __syncthreads();
    __shared__ u32 s_last;
    if (t == 0) s_last = (atomicAdd(&g_done, 1) == gridDim.x - 1) ? 1u : 0u;
    __syncthreads();
    if (!s_last) return;

    __shared__ int part[256];
    __shared__ int sbin[256];
    __shared__ int s_seg1, s_cum1, s_seg2, s_cum2;
    for (int b = 0; b < B; b++) {
        int* h = &g_hist[b << 16];
        const int4* h4 = (const int4*)(h + t * 256);
        int sum = 0;
#pragma unroll 8
        for (int k = 0; k < 64; k++) { int4 v = h4[k]; sum += v.x + v.y + v.z + v.w; }
        part[t] = sum;
        __syncthreads();
        if (t == 0) {
            int cum = 0, seg = 255;
            for (; seg > 0; seg--) { if (cum + part[seg] >= K_PRE) break; cum += part[seg]; }
            s_seg1 = seg; s_cum1 = cum;
            cum = 0; seg = 255;
            for (; seg > 0; seg--) { if (cum + part[seg] >= K_SPEC) break; cum += part[seg]; }
            s_seg2 = seg; s_cum2 = cum;
        }
        __syncthreads();
        sbin[t] = h[s_seg1 * 256 + t];
        __syncthreads();
        if (t == 0) {
            int cum = s_cum1, bin = 255;
            for (;; bin--) { int c = sbin[bin]; if (cum + c >= K_PRE || bin == 0) break; cum += c; }
            g_T16[b] = (u32)(s_seg1 * 256 + bin);
        }
        __syncthreads();
        sbin[t] = h[s_seg2 * 256 + t];
        __syncthreads();
        if (t == 0) {
            int cum = s_cum2, bin = 255;
            for (;; bin--) { int c = sbin[bin]; if (cum + c >= K_SPEC || bin == 0) break; cum += c; }
            g_T16s[b] = (u32)(s_seg2 * 256 + bin);
        }
        __syncthreads();
    }
    int4 z = make_int4(0, 0, 0, 0);
    for (int b = 0; b < B; b++) {
        int4* hz = (int4*)&g_hist[b << 16];
        for (int k = t; k < 16384; k += 256) hz[k] = z;
    }
    if (t == 0) g_done = 0;
}

// ---------- 2: compact full + spec candidate sets ----------
__global__ void k_compact(const float* __restrict__ scores, int B, int N) {
    int idx = blockIdx.x * blockDim.x + threadIdx.x;
    if (idx >= B * N) return;
    int b = idx / N;
    int i = idx - b * N;
    float2 sp = ((const float2*)scores)[idx];
    u32 u = score_map(sp.y);
    u32 hi = u >> 16;
    if (hi >= g_T16[b]) {
        u64 key = ((u64)u << 32) | (u32)(0xFFFFFFFFu - (u32)i);
        int p = atomicAdd(&g_ccount[b], 1);
        if (p < CAP) g_cand[b * CAP + p] = key;
        if (hi >= g_T16s[b]) {
            int q = atomicAdd(&g_scount[b], 1);
            if (q < SCAP) g_scand[b * SCAP + q] = key;
        }
    }
}

// ---------- 3: spec rank (full tile in smem) + decode, one kernel ----------
__global__ void k_rgspec(const float* __restrict__ deltas, const float* __restrict__ iminfo,
                         const float* __restrict__ anchors, int N) {
    __shared__ u64 tile[SCAP];
    int b = blockIdx.y;
    int C2 = g_scount[b];
    if (C2 > SCAP) { if (blockIdx.x == 0 && threadIdx.x == 0) g_full = 1; return; }
    if ((int)blockIdx.x * 128 >= C2) return;
    int C2p = (C2 + 3) & ~3;
    for (int t = threadIdx.x; t < C2p; t += 128)
        tile[t] = (t < C2) ? g_scand[b * SCAP + t] : 0ull;
    __syncthreads();
    int j = blockIdx.x * 128 + threadIdx.x;
    if (j >= C2) return;
    u64 my = tile[j];
    int rank = 0;
#pragma unroll 4
    for (int t = 0; t < C2p; t++) rank += (tile[t] > my) ? 1 : 0;
    decode_write(b, rank, (u32)(my & 0xFFFFFFFFull), deltas, iminfo, anchors, N);
}

// ---------- 4: speculative IoU mask (rows/cols < 2048) ----------
__global__ void k_mask_spec(void) {
    __shared__ float sx1[64], sy1[64], sx2[64], sy2[64], sar[64];
    int cc = blockIdx.x;      // 0..SPEC_W-1
    int rt = blockIdx.y;      // 0..SPEC_RT-1
    if (cc < rt * 4) return;
    int bset = blockIdx.z;
    int t = threadIdx.x;      // 256
    int jg0 = cc * 64;
    if (t < 64) {
        float4 bj = g_box[bset * NROW + jg0 + t];
        sx1[t] = bj.x; sy1[t] = bj.y; sx2[t] = bj.z; sy2[t] = bj.w;
        sar[t] = g_area[bset * NROW + jg0 + t];
    }
    __syncthreads();
    int i = rt * 256 + t;
    if (i >= NROW) return;
    float4 bi = g_box[bset * NROW + i];
    float ai = g_area[bset * NROW + i];
    u64 word = 0;
#pragma unroll 4
    for (int k = 0; k < 64; k++) {
        if (jg0 + k > i && iou_sup(bi, ai, sx1[k], sy1[k], sx2[k], sy2[k], sar[k]))
            word |= 1ull << k;
    }
    g_mask[((size_t)bset * NROW + i) * WSTRIDE + cc] = word;
}

// ---------- 5: spec greedy scan + fused output ----------
__global__ void k_scan_out_spec(float* __restrict__ out, int B) {
    if (g_full) return;
    __shared__ u64 sh_keep[2][SPEC_W];
    __shared__ u64 sh_diag[2][64];
    __shared__ u64 sh_next[2], sh_cur[2];
    __shared__ int sh_comb, sh_done;
    __shared__ u64 comb[SPEC_W];
    __shared__ int pref[SPEC_W];
    __shared__ int s_nk;
    int b = blockIdx.x;
    int t = threadIdx.x;          // 128
    int set = t >> 6, lt = t & 63;
    const u64* M = &g_mask[(size_t)(b * 2 + set) * NROW * WSTRIDE];
    if (t == 0) { sh_comb = 0; sh_done = 0; sh_cur[0] = 0; sh_cur[1] = 0; }
    __syncthreads();
    int c = 0;
    for (; c < SPEC_W; c++) {
        sh_diag[set][lt] = M[(size_t)(c * 64 + lt) * WSTRIDE + c];
        __syncthreads();
        if (lt == 0) {
            u64 cur = sh_cur[set], keep = 0;
            for (int k = 0; k < 64; k++)
                if (!((cur >> k) & 1ull)) { keep |= 1ull << k; cur |= sh_diag[set][k]; }
            sh_keep[set][c] = keep;
        }
        __syncthreads();
        if (t == 0) {
            sh_comb += __popcll(sh_keep[0][c] & sh_keep[1][c]);
            if (sh_comb >= K_POST) sh_done = 1;
        }
        if (t < 2) sh_next[t] = 0;                 // safe: old sh_next consumed before last sync
        __syncthreads();
        if (sh_done) { c++; break; }
        if (c + 1 < SPEC_W) {
            u64 acc = 0;
            for (int r = lt; r < (c + 1) * 64; r += 64)
                if ((sh_keep[set][r >> 6] >> (r & 63)) & 1ull)
                    acc |= M[(size_t)r * WSTRIDE + (c + 1)];
            for (int o = 16; o; o >>= 1) acc |= __shfl_xor_sync(0xffffffffu, acc, o);
            if ((t & 31) == 0 && acc) atomicOr((unsigned long long*)&sh_next[set], acc);
            __syncthreads();
            if (lt == 0) sh_cur[set] = sh_next[set];
            __syncthreads();                       // read-before-zero barrier (race fix)
        }
    }
    if (!sh_done) { if (t == 0) g_full = 1; return; }
    // fused output
    int chunks = c;
    float* outL = out + (size_t)b * K_POST * 5;
    float* outR = out + (size_t)(B + b) * K_POST * 5;
    for (int i = t; i < K_POST * 5; i += 128) {
        float v = (i % 5 == 0) ? (float)b : 0.f;
        outL[i] = v; outR[i] = v;
    }
    for (int w = t; w < SPEC_W; w += 128)
        comb[w] = (w < chunks) ? (sh_keep[0][w] & sh_keep[1][w]) : 0ull;
    __syncthreads();
    if (t == 0) {
        int s = 0;
        for (int w = 0; w < SPEC_W; w++) { pref[w] = s; s += __popcll(comb[w]); }
        s_nk = s < K_POST ? s : K_POST;
    }
    __syncthreads();
    int nk = s_nk;
    for (int w = t; w < SPEC_W; w += 128) {
        int rank = pref[w];
        u64 m = comb[w];
        while (m && rank < nk) {
            int k = __ffsll((long long)m) - 1; m &= m - 1;
            int r = w * 64 + k;
            float4 bl = g_box[(b * 2 + 0) * NROW + r];
            float4 br = g_box[(b * 2 + 1) * NROW + r];
            outL[rank * 5 + 1] = bl.x; outL[rank * 5 + 2] = bl.y;
            outL[rank * 5 + 3] = bl.z; outL[rank * 5 + 4] = bl.w;
            outR[rank * 5 + 1] = br.x; outR[rank * 5 + 2] = br.y;
            outR[rank * 5 + 3] = br.z; outR[rank * 5 + 4] = br.w;
            rank++;
        }
    }
}

// ---------- 6: monolithic guarded fallback (exact, slow, never taken in practice)
//              + always-on counter cleanup ----------
__global__ void __launch_bounds__(1024) k_fallback(float* __restrict__ out,
        const float* __restrict__ deltas, const float* __restrict__ iminfo,
        const float* __restrict__ anchors, int B, int N) {
    __shared__ u64 tile[FB_TILE];
    __shared__ float sx1[64], sy1[64], sx2[64], sy2[64], sar[64];
    __shared__ u64 sh_keep[2][NWORD];
    __shared__ u64 sh_diag[64];
    __shared__ u64 sh_cur, sh_next;
    __shared__ u64 comb[NWORD];
    __shared__ int pref[NWORD];
    __shared__ int s_nk;
    int b = blockIdx.x;
    int tx = threadIdx.x;     // 1024
    int go = g_full;
    int C = g_ccount[b]; if (C > CAP) C = CAP;
    if (go) {
        // exact ranks for all candidates, then decode
        u64 my[16]; int rk[16]; int nj = 0;
        for (int j = tx; j < C && nj < 16; j += 1024) { my[nj] = g_cand[b * CAP + j]; rk[nj] = 0; nj++; }
        for (int c0 = 0; c0 < C; c0 += FB_TILE) {
            int nt = min(FB_TILE, C - c0);
            __syncthreads();
            for (int t2 = tx; t2 < nt; t2 += 1024) tile[t2] = g_cand[b * CAP + c0 + t2];
            __syncthreads();
            for (int t2 = 0; t2 < nt; t2++) {
                u64 v = tile[t2];
                for (int k = 0; k < nj; k++) rk[k] += (v > my[k]) ? 1 : 0;
            }
        }
        for (int k = 0; k < nj; k++)
            if (rk[k] < K_PRE)
                decode_write(b, rk[k], (u32)(my[k] & 0xFFFFFFFFull), deltas, iminfo, anchors, N);
        __syncthreads();
        __threadfence();
        __syncthreads();
        // full triangular mask, both sets
        for (int set = 0; set < 2; set++) {
            int bset = b * 2 + set;
            for (int cc = 0; cc < NWORD; cc++) {
                __syncthreads();
                if (tx < 64) {
                    float4 bj = g_box[bset * NROW + cc * 64 + tx];
                    sx1[tx] = bj.x; sy1[tx] = bj.y; sx2[tx] = bj.z; sy2[tx] = bj.w;
                    sar[tx] = g_area[bset * NROW + cc * 64 + tx];
                }
                __syncthreads();
                for (int i = tx; i < NROW; i += 1024) {
                    if ((i >> 6) > cc) continue;
                    float4 bi = g_box[bset * NROW + i];
                    float ai = g_area[bset * NROW + i];
                    u64 word = 0;
                    for (int k = 0; k < 64; k++)
                        if (cc * 64 + k > i && iou_sup(bi, ai, sx1[k], sy1[k], sx2[k], sy2[k], sar[k]))
                            word |= 1ull << k;
                    g_mask[((size_t)bset * NROW + i) * WSTRIDE + cc] = word;
                }
            }
        }
        __syncthreads();
        __threadfence();
        __syncthreads();
        // full greedy scan, sets sequential
        for (int set = 0; set < 2; set++) {
            const u64* M = &g_mask[(size_t)(b * 2 + set) * NROW * WSTRIDE];
            if (tx == 0) sh_cur = 0;
            __syncthreads();
            for (int c = 0; c < NWORD; c++) {
                if (tx < 64) sh_diag[tx] = M[(size_t)(c * 64 + tx) * WSTRIDE + c];
                __syncthreads();
                if (tx == 0) {
                    u64 cur = sh_cur, keep = 0;
                    int lim = min(64, K_PRE - c * 64);
                    for (int k = 0; k < lim; k++)
                        if (!((cur >> k) & 1ull)) { keep |= 1ull << k; cur |= sh_diag[k]; }
                    sh_keep[set][c] = keep;
                    sh_next = 0;
                }
                __syncthreads();
                if (c + 1 < NWORD) {
                    u64 acc = 0;
                    for (int r = tx; r < (c + 1) * 64; r += 1024)
                        if ((sh_keep[set][r >> 6] >> (r & 63)) & 1ull)
                            acc |= M[(size_t)r * WSTRIDE + (c + 1)];
                    for (int o = 16; o; o >>= 1) acc |= __shfl_xor_sync(0xffffffffu, acc, o);
                    if ((tx & 31) == 0 && acc) atomicOr((unsigned long long*)&sh_next, acc);
                    __syncthreads();
                    if (tx == 0) sh_cur = sh_next;
                    __syncthreads();
                }
            }
            __syncthreads();
        }
        // emit
        float* outL = out + (size_t)b * K_POST * 5;
        float* outR = out + (size_t)(B + b) * K_POST * 5;
        for (int i = tx; i < K_POST * 5; i += 1024) {
            float v = (i % 5 == 0) ? (float)b : 0.f;
            outL[i] = v; outR[i] = v;
        }
        for (int w = tx; w < NWORD; w += 1024) comb[w] = sh_keep[0][w] & sh_keep[1][w];
        __syncthreads();
        if (tx == 0) {
            int s = 0;
            for (int w = 0; w < NWORD; w++) { pref[w] = s; s += __popcll(comb[w]); }
            s_nk = s < K_POST ? s : K_POST;
        }
        __syncthreads();
        int nk = s_nk;
        for (int w = tx; w < NWORD; w += 1024) {
            int rank = pref[w];
            u64 m = comb[w];
            while (m && rank < nk) {
                int k = __ffsll((long long)m) - 1; m &= m - 1;
                int r = w * 64 + k;
                float4 bl = g_box[(b * 2 + 0) * NROW + r];
                float4 br = g_box[(b * 2 + 1) * NROW + r];
                outL[rank * 5 + 1] = bl.x; outL[rank * 5 + 2] = bl.y;
                outL[rank * 5 + 3] = bl.z; outL[rank * 5 + 4] = bl.w;
                outR[rank * 5 + 1] = br.x; outR[rank * 5 + 2] = br.y;
                outR[rank * 5 + 3] = br.z; outR[rank * 5 + 4] = br.w;
                rank++;
            }
        }
        __syncthreads();
    }
    if (tx == 0) { g_ccount[b] = 0; g_scount[b] = 0; if (b == 0) g_full = 0; }
}

extern "C" void kernel_launch(void* const* d_in, const int* in_sizes, int n_in,
                              void* d_out, int out_size) {
    const float* scores  = (const float*)d_in[0];
    const float* deltas  = (const float*)d_in[1];
    const float* iminfo  = (const float*)d_in[2];
    const float* anchors = (const float*)d_in[3];
    float* out = (float*)d_out;
    int B = in_sizes[2] / 3;
    int N = in_sizes[3] / 4;
    int g = (B * N + 255) / 256;

    k_hist<<<g, 256>>>(scores, B, N);
    k_compact<<<g, 256>>>(scores, B, N);
    k_rgspec<<<dim3(SCAP / 128, B), 128>>>(deltas, iminfo, anchors, N);
    k_mask_spec<<<dim3(SPEC_W, SPEC_RT, 2 * B), 256>>>();
    k_scan_out_spec<<<B, 128>>>(out, B);
    k_fallback<<<B, 1024>>>(out, deltas, iminfo, anchors, B, N);
}

// round 9
// speedup vs baseline: 3.6453x; 1.7941x over previous
#include <cuda_runtime.h>
#include <cstdint>
#include <math.h>

typedef unsigned long long u64;
typedef unsigned int u32;

#define K_PRE 6000
#define K_SPEC 1024
#define K_POST 300
#define NMS_TH 0.7f
#define CONS_TH 0.99f
#define NROW 6016
#define NWORD 94
#define WSTRIDE 96
#define MAXB 2
#define CAP 16384
#define SCAP 4096
#define SPEC_W 16
#define SPEC_RT 4
#define FB_TILE 2048

// ---------- persistent device scratch (self-cleaning across graph replays) ----------
__device__ int    g_hist[MAXB * 65536];     // used (and zeroed) only by fallback
__device__ u32    g_mdone;                   // mask-kernel arrival counter (reset by last block)
__device__ int    g_ccount[MAXB], g_scount[MAXB];   // zeroed by k_fallback (always)
__device__ u64    g_cand[MAXB * CAP];
__device__ u64    g_scand[MAXB * SCAP];
__device__ float4 g_box[2 * MAXB * NROW];
__device__ float  g_area[2 * MAXB * NROW];
__device__ u64    g_mask[(size_t)2 * MAXB * NROW * WSTRIDE];
__device__ int    g_full;                    // reset by k_fallback

__device__ __forceinline__ u32 score_map(float s) {
    u32 u = __float_as_uint(s);
    return (u & 0x80000000u) ? ~u : (u | 0x80000000u);
}

__device__ __forceinline__ bool iou_sup(float4 bi, float ai,
                                        float x1, float y1, float x2, float y2, float ar) {
    float xx1 = fmaxf(bi.x, x1), yy1 = fmaxf(bi.y, y1);
    float xx2 = fminf(bi.z, x2), yy2 = fminf(bi.w, y2);
    float ow = xx2 - xx1 + 1.0f, oh = yy2 - yy1 + 1.0f;
    if (!(ow > 0.0f && oh > 0.0f)) return false;
    float inter = ow * oh;
    float uni = ai + ar - inter;
    float p = NMS_TH * uni;
    bool sup = inter > p;
    if (fabsf(inter - p) <= 1e-5f * uni)     // borderline: exact IEEE decision
        sup = __fdiv_rn(inter, uni) > NMS_TH;
    return sup;
}

__device__ __forceinline__ void decode_write(int b, int rank, u32 lo,
        const float* __restrict__ deltas, const float* __restrict__ iminfo,
        const float* __restrict__ anchors, int N) {
    int i = (int)(0xFFFFFFFFu - lo);
    const float* a = anchors + (size_t)i * 4;
    float w = a[2] - a[0] + 1.0f;
    float h = a[3] - a[1] + 1.0f;
    float cx = a[0] + 0.5f * w;
    float cy = a[1] + 0.5f * h;
    const float* d = deltas + ((size_t)b * N + i) * 6;
    float Hm1 = iminfo[b * 3 + 0] - 1.0f;
    float Wm1 = iminfo[b * 3 + 1] - 1.0f;
    float eh = (float)exp((double)d[3]) * h;   // accurate exp (fast-math safe)
    float pcy = d[1] * h + cy;
    float y1 = fminf(fmaxf(pcy - 0.5f * eh, 0.f), Hm1);
    float y2 = fminf(fmaxf(pcy + 0.5f * eh, 0.f), Hm1);
    {
        float pcx = d[0] * w + cx;
        float pw = (float)exp((double)d[2]) * w;
        float x1 = fminf(fmaxf(pcx - 0.5f * pw, 0.f), Wm1);
        float x2 = fminf(fmaxf(pcx + 0.5f * pw, 0.f), Wm1);
        g_box[(b * 2 + 0) * NROW + rank] = make_float4(x1, y1, x2, y2);
        g_area[(b * 2 + 0) * NROW + rank] = (x2 - x1 + 1.0f) * (y2 - y1 + 1.0f);
    }
    {
        float pcx = d[4] * w + cx;
        float pw = (float)exp((double)d[5]) * w;
        float x1 = fminf(fmaxf(pcx - 0.5f * pw, 0.f), Wm1);
        float x2 = fminf(fmaxf(pcx + 0.5f * pw, 0.f), Wm1);
        g_box[(b * 2 + 1) * NROW + rank] = make_float4(x1, y1, x2, y2);
        g_area[(b * 2 + 1) * NROW + rank] = (x2 - x1 + 1.0f) * (y2 - y1 + 1.0f);
    }
}

// ---------- 1: single-pass conservative compaction (s >= CONS_TH) ----------
__global__ void k_compact(const float* __restrict__ scores, int B, int N) {
    int idx = blockIdx.x * blockDim.x + threadIdx.x;
    if (idx >= B * N) return;
    int b = idx / N;
    int i = idx - b * N;
    float2 sp = ((const float2*)scores)[idx];
    if (sp.y >= CONS_TH) {
        u32 u = score_map(sp.y);
        int q = atomicAdd(&g_scount[b], 1);
        if (q < SCAP)
            g_scand[b * SCAP + q] = ((u64)u << 32) | (u32)(0xFFFFFFFFu - (u32)i);
    }
}

// ---------- 2: validate + exact rank (smem tile) + decode ----------
__global__ void k_rgspec(const float* __restrict__ deltas, const float* __restrict__ iminfo,
                         const float* __restrict__ anchors, int N) {
    __shared__ u64 tile[SCAP];
    int b = blockIdx.y;
    int C2 = g_scount[b];
    if (C2 < K_SPEC || C2 > SCAP) {          // spec set not provably rank-closed -> exact path
        if (blockIdx.x == 0 && threadIdx.x == 0) g_full = 1;
        return;
    }
    if ((int)blockIdx.x * 128 >= C2) return;
    int C2p = (C2 + 3) & ~3;
    for (int t = threadIdx.x; t < C2p; t += 128)
        tile[t] = (t < C2) ? g_scand[b * SCAP + t] : 0ull;
    __syncthreads();
    int j = blockIdx.x * 128 + threadIdx.x;
    if (j >= C2) return;
    u64 my = tile[j];
    int rank = 0;
#pragma unroll 4
    for (int t = 0; t < C2p; t++) rank += (tile[t] > my) ? 1 : 0;
    decode_write(b, rank, (u32)(my & 0xFFFFFFFFull), deltas, iminfo, anchors, N);
}

// ---------- 3: spec IoU mask (1024x1024) + last-block scan + emit ----------
__global__ void k_mask_scan(float* __restrict__ out, int B) {
    // ---- mask phase ----
    {
        __shared__ float sx1[64], sy1[64], sx2[64], sy2[64], sar[64];
        int cc = blockIdx.x;      // 0..SPEC_W-1
        int rt = blockIdx.y;      // 0..SPEC_RT-1
        int bset = blockIdx.z;
        int t = threadIdx.x;      // 256
        if (cc >= rt * 4) {
            int jg0 = cc * 64;
            if (t < 64) {
                float4 bj = g_box[bset * NROW + jg0 + t];
                sx1[t] = bj.x; sy1[t] = bj.y; sx2[t] = bj.z; sy2[t] = bj.w;
                sar[t] = g_area[bset * NROW + jg0 + t];
            }
            __syncthreads();
            int i = rt * 256 + t;
            float4 bi = g_box[bset * NROW + i];
            float ai = g_area[bset * NROW + i];
            u64 word = 0;
#pragma unroll 4
            for (int k = 0; k < 64; k++) {
                if (jg0 + k > i && iou_sup(bi, ai, sx1[k], sy1[k], sx2[k], sy2[k], sar[k]))
                    word |= 1ull << k;
            }
            g_mask[((size_t)bset * NROW + i) * WSTRIDE + cc] = word;
        }
    }
    __threadfence();
    __shared__ u32 s_last;
    if (threadIdx.x == 0) {
        u32 total = gridDim.x * gridDim.y * gridDim.z;
        s_last = (atomicAdd(&g_mdone, 1) == total - 1) ? 1u : 0u;
    }
    __syncthreads();
    if (!s_last) return;
    if (threadIdx.x == 0) g_mdone = 0;       // reset for next replay
    if (g_full) return;                       // fallback will produce output

    // ---- scan + emit (one block, both images sequentially) ----
    __shared__ u64 sh_keep[2][SPEC_W];
    __shared__ u64 sh_diag[2][64];
    __shared__ u64 sh_next[2], sh_cur[2];
    __shared__ int sh_comb, sh_done, s_nk;
    __shared__ u64 comb[SPEC_W];
    __shared__ int pref[SPEC_W];
    int t = threadIdx.x;          // 256
    int set = (t >> 6) & 1;
    int lt = t & 63;
    bool act = t < 128;
    for (int b = 0; b < B; b++) {
        const u64* M = &g_mask[(size_t)(b * 2 + set) * NROW * WSTRIDE];
        if (t == 0) { sh_comb = 0; sh_done = 0; sh_cur[0] = 0; sh_cur[1] = 0; }
        __syncthreads();
        int c = 0;
        for (; c < SPEC_W; c++) {
            if (act) sh_diag[set][lt] = M[(size_t)(c * 64 + lt) * WSTRIDE + c];
            __syncthreads();
            if (act && lt == 0) {
                u64 cur = sh_cur[set], keep = 0;
                for (int k = 0; k < 64; k++)
                    if (!((cur >> k) & 1ull)) { keep |= 1ull << k; cur |= sh_diag[set][k]; }
                sh_keep[set][c] = keep;
            }
            __syncthreads();
            if (t == 0) {
                sh_comb += __popcll(sh_keep[0][c] & sh_keep[1][c]);
                if (sh_comb >= K_POST) sh_done = 1;
            }
            if (t < 2) sh_next[t] = 0;
            __syncthreads();
            if (sh_done) { c++; break; }
            if (c + 1 < SPEC_W) {
                if (act) {
                    u64 acc = 0;
                    for (int r = lt; r < (c + 1) * 64; r += 64)
                        if ((sh_keep[set][r >> 6] >> (r & 63)) & 1ull)
                            acc |= M[(size_t)r * WSTRIDE + (c + 1)];
                    for (int o = 16; o; o >>= 1) acc |= __shfl_xor_sync(0xffffffffu, acc, o);
                    if ((t & 31) == 0 && acc) atomicOr((unsigned long long*)&sh_next[set], acc);
                }
                __syncthreads();
                if (act && lt == 0) sh_cur[set] = sh_next[set];
                __syncthreads();
            }
        }
        if (!sh_done) {                       // not enough combined keeps in prefix
            if (t == 0) g_full = 1;
            return;
        }
        int chunks = c;
        float* outL = out + (size_t)b * K_POST * 5;
        float* outR = out + (size_t)(B + b) * K_POST * 5;
        for (int i = t; i < K_POST * 5; i += 256) {
            float v = (i % 5 == 0) ? (float)b : 0.f;
            outL[i] = v; outR[i] = v;
        }
        for (int w = t; w < SPEC_W; w += 256)
            comb[w] = (w < chunks) ? (sh_keep[0][w] & sh_keep[1][w]) : 0ull;
        __syncthreads();
        if (t == 0) {
            int s = 0;
            for (int w = 0; w < SPEC_W; w++) { pref[w] = s; s += __popcll(comb[w]); }
            s_nk = s < K_POST ? s : K_POST;
        }
        __syncthreads();
        int nk = s_nk;
        for (int w = t; w < SPEC_W; w += 256) {
            int rank = pref[w];
            u64 m = comb[w];
            while (m && rank < nk) {
                int k = __ffsll((long long)m) - 1; m &= m - 1;
                int r = w * 64 + k;
                float4 bl = g_box[(b * 2 + 0) * NROW + r];
                float4 br = g_box[(b * 2 + 1) * NROW + r];
                outL[rank * 5 + 1] = bl.x; outL[rank * 5 + 2] = bl.y;
                outL[rank * 5 + 3] = bl.z; outL[rank * 5 + 4] = bl.w;
                outR[rank * 5 + 1] = br.x; outR[rank * 5 + 2] = br.y;
                outR[rank * 5 + 3] = br.z; outR[rank * 5 + 4] = br.w;
                rank++;
            }
        }
        __syncthreads();
    }
}

// ---------- 4: self-sufficient exact fallback (guarded) + always-on cleanup ----------
__global__ void __launch_bounds__(1024) k_fallback(float* __restrict__ out,
        const float* __restrict__ scores,
        const float* __restrict__ deltas, const float* __restrict__ iminfo,
        const float* __restrict__ anchors, int B, int N) {
    __shared__ u64 tile[FB_TILE];
    __shared__ int part[1024];
    __shared__ int s_T16;
    __shared__ float sx1[64], sy1[64], sx2[64], sy2[64], sar[64];
    __shared__ u64 sh_keep[2][NWORD];
    __shared__ u64 sh_diag[64];
    __shared__ u64 sh_cur, sh_next;
    __shared__ u64 comb[NWORD];
    __shared__ int pref[NWORD];
    __shared__ int s_nk;
    int b = blockIdx.x;
    int tx = threadIdx.x;     // 1024
    int go = g_full;
    if (go) {
        // --- exact selection from raw scores: histogram -> threshold -> collect ---
        int* h = &g_hist[b << 16];
        for (int k = tx; k < 65536; k += 1024) h[k] = 0;
        __syncthreads();
        const float2* sc = ((const float2*)scores) + (size_t)b * N;
        for (int idx = tx; idx < N; idx += 1024) {
            u32 u = score_map(sc[idx].y);
            atomicAdd(&h[u >> 16], 1);
        }
        __syncthreads();
        int sum = 0;
        for (int k = 0; k < 64; k++) sum += h[tx * 64 + k];
        part[tx] = sum;
        __syncthreads();
        if (tx == 0) {
            int cum = 0, seg = 1023;
            for (; seg > 0; seg--) { if (cum + part[seg] >= K_PRE) break; cum += part[seg]; }
            int bin = seg * 64 + 63, lo = seg * 64;
            for (;; bin--) { int c = h[bin]; if (cum + c >= K_PRE || bin == lo) break; cum += c; }
            s_T16 = bin;
        }
        __syncthreads();
        u32 T16 = (u32)s_T16;
        for (int idx = tx; idx < N; idx += 1024) {
            u32 u = score_map(sc[idx].y);
            if ((u >> 16) >= T16) {
                int p = atomicAdd(&g_ccount[b], 1);
                if (p < CAP)
                    g_cand[b * CAP + p] = ((u64)u << 32) | (u32)(0xFFFFFFFFu - (u32)idx);
            }
        }
        __syncthreads();
        int C = g_ccount[b]; if (C > CAP) C = CAP;
        // --- exact ranks + decode ---
        u64 my[16]; int rk[16]; int nj = 0;
        for (int j = tx; j < C && nj < 16; j += 1024) { my[nj] = g_cand[b * CAP + j]; rk[nj] = 0; nj++; }
        for (int c0 = 0; c0 < C; c0 += FB_TILE) {
            int nt = min(FB_TILE, C - c0);
            __syncthreads();
            for (int t2 = tx; t2 < nt; t2 += 1024) tile[t2] = g_cand[b * CAP + c0 + t2];
            __syncthreads();
            for (int t2 = 0; t2 < nt; t2++) {
                u64 v = tile[t2];
                for (int k = 0; k < nj; k++) rk[k] += (v > my[k]) ? 1 : 0;
            }
        }
        for (int k = 0; k < nj; k++)
            if (rk[k] < K_PRE)
                decode_write(b, rk[k], (u32)(my[k] & 0xFFFFFFFFull), deltas, iminfo, anchors, N);
        __syncthreads();
        __threadfence();
        __syncthreads();
        // --- full triangular mask, both sets ---
        for (int set = 0; set < 2; set++) {
            int bset = b * 2 + set;
            for (int cc = 0; cc < NWORD; cc++) {
                __syncthreads();
                if (tx < 64) {
                    float4 bj = g_box[bset * NROW + cc * 64 + tx];
                    sx1[tx] = bj.x; sy1[tx] = bj.y; sx2[tx] = bj.z; sy2[tx] = bj.w;
                    sar[tx] = g_area[bset * NROW + cc * 64 + tx];
                }
                __syncthreads();
                for (int i = tx; i < NROW; i += 1024) {
                    if ((i >> 6) > cc) continue;
                    float4 bi = g_box[bset * NROW + i];
                    float ai = g_area[bset * NROW + i];
                    u64 word = 0;
                    for (int k = 0; k < 64; k++)
                        if (cc * 64 + k > i && iou_sup(bi, ai, sx1[k], sy1[k], sx2[k], sy2[k], sar[k]))
                            word |= 1ull << k;
                    g_mask[((size_t)bset * NROW + i) * WSTRIDE + cc] = word;
                }
            }
        }
        __syncthreads();
        __threadfence();
        __syncthreads();
        // --- full greedy scan, sets sequential ---
        for (int set = 0; set < 2; set++) {
            const u64* M = &g_mask[(size_t)(b * 2 + set) * NROW * WSTRIDE];
            if (tx == 0) sh_cur = 0;
            __syncthreads();
            for (int c = 0; c < NWORD; c++) {
                if (tx < 64) sh_diag[tx] = M[(size_t)(c * 64 + tx) * WSTRIDE + c];
                __syncthreads();
                if (tx == 0) {
                    u64 cur = sh_cur, keep = 0;
                    int lim = min(64, K_PRE - c * 64);
                    for (int k = 0; k < lim; k++)
                        if (!((cur >> k) & 1ull)) { keep |= 1ull << k; cur |= sh_diag[k]; }
                    sh_keep[set][c] = keep;
                    sh_next = 0;
                }
                __syncthreads();
                if (c + 1 < NWORD) {
                    u64 acc = 0;
                    for (int r = tx; r < (c + 1) * 64; r += 1024)
                        if ((sh_keep[set][r >> 6] >> (r & 63)) & 1ull)
                            acc |= M[(size_t)r * WSTRIDE + (c + 1)];
                    for (int o = 16; o; o >>= 1) acc |= __shfl_xor_sync(0xffffffffu, acc, o);
                    if ((tx & 31) == 0 && acc) atomicOr((unsigned long long*)&sh_next, acc);
                    __syncthreads();
                    if (tx == 0) sh_cur = sh_next;
                    __syncthreads();
                }
            }
            __syncthreads();
        }
        // --- emit ---
        float* outL = out + (size_t)b * K_POST * 5;
        float* outR = out + (size_t)(B + b) * K_POST * 5;
        for (int i = tx; i < K_POST * 5; i += 1024) {
            float v = (i % 5 == 0) ? (float)b : 0.f;
            outL[i] = v; outR[i] = v;
        }
        for (int w = tx; w < NWORD; w += 1024) comb[w] = sh_keep[0][w] & sh_keep[1][w];
        __syncthreads();
        if (tx == 0) {
            int s = 0;
            for (int w = 0; w < NWORD; w++) { pref[w] = s; s += __popcll(comb[w]); }
            s_nk = s < K_POST ? s : K_POST;
        }
        __syncthreads();
        int nk = s_nk;
        for (int w = tx; w < NWORD; w += 1024) {
            int rank = pref[w];
            u64 m = comb[w];
            while (m && rank < nk) {
                int k = __ffsll((long long)m) - 1; m &= m - 1;
                int r = w * 64 + k;
                float4 bl = g_box[(b * 2 + 0) * NROW + r];
                float4 br = g_box[(b * 2 + 1) * NROW + r];
                outL[rank * 5 + 1] = bl.x; outL[rank * 5 + 2] = bl.y;
                outL[rank * 5 + 3] = bl.z; outL[rank * 5 + 4] = bl.w;
                outR[rank * 5 + 1] = br.x; outR[rank * 5 + 2] = br.y;
                outR[rank * 5 + 3] = br.z; outR[rank * 5 + 4] = br.w;
                rank++;
            }
        }
        __syncthreads();
    }
    if (tx == 0) { g_ccount[b] = 0; g_scount[b] = 0; if (b == 0) g_full = 0; }
}

extern "C" void kernel_launch(void* const* d_in, const int* in_sizes, int n_in,
                              void* d_out, int out_size) {
    const float* scores  = (const float*)d_in[0];
    const float* deltas  = (const float*)d_in[1];
    const float* iminfo  = (const float*)d_in[2];
    const float* anchors = (const float*)d_in[3];
    float* out = (float*)d_out;
    int B = in_sizes[2] / 3;
    int N = in_sizes[3] / 4;
    int g = (B * N + 255) / 256;

    k_compact<<<g, 256>>>(scores, B, N);
    k_rgspec<<<dim3(SCAP / 128, B), 128>>>(deltas, iminfo, anchors, N);
    k_mask_scan<<<dim3(SPEC_W, SPEC_RT, 2 * B), 256>>>(out, B);
    k_fallback<<<B, 1024>>>(out, scores, deltas, iminfo, anchors, B, N);
}

// round 11
// speedup vs baseline: 4.0817x; 1.1197x over previous
#include <cuda_runtime.h>
#include <cstdint>
#include <math.h>

typedef unsigned long long u64;
typedef unsigned int u32;

#define K_PRE 6000
#define K_SPEC 1024
#define K_POST 300
#define NMS_TH 0.7f
#define CONS_TH 0.99f
#define NROW 6016
#define NWORD 94
#define WSTRIDE 96
#define MAXB 2
#define CAP 16384
#define SCAP 4096
#define SPEC_W 16
#define GRID 148
#define TPB 256

// ---------- persistent device scratch (self-cleaning across graph replays) ----------
__device__ int    g_hist[MAXB * 65536];
__device__ int    g_T16g[MAXB];
__device__ int    g_ccount[MAXB], g_scount[MAXB];   // zeroed at end of kernel
__device__ u64    g_cand[MAXB * CAP];
__device__ u64    g_scand[MAXB * SCAP];
__device__ float4 g_box[2 * MAXB * NROW];
__device__ float  g_area[2 * MAXB * NROW];
__device__ u64    g_mask[(size_t)2 * MAXB * NROW * WSTRIDE];
__device__ int    g_full;                            // reset at end of kernel
__device__ u32    g_bcnt;                            // barrier arrival count (self-resets)
__device__ volatile u32 g_bgen;                      // barrier generation (monotonic)

__device__ __forceinline__ void gbar() {
    __syncthreads();
    if (threadIdx.x == 0) {
        u32 gen = g_bgen;
        __threadfence();
        if (atomicAdd(&g_bcnt, 1) == GRID - 1) {
            g_bcnt = 0;
            __threadfence();
            g_bgen = gen + 1;
        } else {
            while (g_bgen == gen) { }
        }
        __threadfence();
    }
    __syncthreads();
}

__device__ __forceinline__ u32 score_map(float s) {
    u32 u = __float_as_uint(s);
    return (u & 0x80000000u) ? ~u : (u | 0x80000000u);
}

__device__ __forceinline__ bool iou_sup(float4 bi, float ai,
                                        float x1, float y1, float x2, float y2, float ar) {
    float xx1 = fmaxf(bi.x, x1), yy1 = fmaxf(bi.y, y1);
    float xx2 = fminf(bi.z, x2), yy2 = fminf(bi.w, y2);
    float ow = xx2 - xx1 + 1.0f, oh = yy2 - yy1 + 1.0f;
    if (!(ow > 0.0f && oh > 0.0f)) return false;
    float inter = ow * oh;
    float uni = ai + ar - inter;
    float p = NMS_TH * uni;
    bool sup = inter > p;
    if (fabsf(inter - p) <= 1e-5f * uni)     // borderline: exact IEEE decision
        sup = __fdiv_rn(inter, uni) > NMS_TH;
    return sup;
}

__device__ __forceinline__ void decode_write(int b, int rank, u32 lo,
        const float* __restrict__ deltas, const float* __restrict__ iminfo,
        const float* __restrict__ anchors, int N) {
    int i = (int)(0xFFFFFFFFu - lo);
    const float* a = anchors + (size_t)i * 4;
    float w = a[2] - a[0] + 1.0f;
    float h = a[3] - a[1] + 1.0f;
    float cx = a[0] + 0.5f * w;
    float cy = a[1] + 0.5f * h;
    const float* d = deltas + ((size_t)b * N + i) * 6;
    float Hm1 = iminfo[b * 3 + 0] - 1.0f;
    float Wm1 = iminfo[b * 3 + 1] - 1.0f;
    float eh = (float)exp((double)d[3]) * h;   // accurate exp (fast-math safe)
    float pcy = d[1] * h + cy;
    float y1 = fminf(fmaxf(pcy - 0.5f * eh, 0.f), Hm1);
    float y2 = fminf(fmaxf(pcy + 0.5f * eh, 0.f), Hm1);
    {
        float pcx = d[0] * w + cx;
        float pw = (float)exp((double)d[2]) * w;
        float x1 = fminf(fmaxf(pcx - 0.5f * pw, 0.f), Wm1);
        float x2 = fminf(fmaxf(pcx + 0.5f * pw, 0.f), Wm1);
        g_box[(b * 2 + 0) * NROW + rank] = make_float4(x1, y1, x2, y2);
        g_area[(b * 2 + 0) * NROW + rank] = (x2 - x1 + 1.0f) * (y2 - y1 + 1.0f);
    }
    {
        float pcx = d[4] * w + cx;
        float pw = (float)exp((double)d[5]) * w;
        float x1 = fminf(fmaxf(pcx - 0.5f * pw, 0.f), Wm1);
        float x2 = fminf(fmaxf(pcx + 0.5f * pw, 0.f), Wm1);
        g_box[(b * 2 + 1) * NROW + rank] = make_float4(x1, y1, x2, y2);
        g_area[(b * 2 + 1) * NROW + rank] = (x2 - x1 + 1.0f) * (y2 - y1 + 1.0f);
    }
}

extern "C" __global__ void __launch_bounds__(TPB) k_all(
    float* __restrict__ out,
    const float* __restrict__ scores,
    const float* __restrict__ deltas,
    const float* __restrict__ iminfo,
    const float* __restrict__ anchors,
    int B, int N)
{
    __shared__ u64   sh_tile[SCAP];                 // 32KB rank tile
    __shared__ float sbx1[64], sby1[64], sbx2[64], sby2[64], sbar[64];
    __shared__ u64   sh_keep[2][NWORD];
    __shared__ u64   sh_diag[2][64];
    __shared__ u64   sh_next[2], sh_cur[2];
    __shared__ int   sh_comb, sh_done, sh_nk;
    __shared__ u64   sh_cw[NWORD];
    __shared__ int   sh_pref[NWORD];
    __shared__ int   sh_part[256];

    int bid = blockIdx.x, tid = threadIdx.x;
    int total = B * N;
    const float2* sc2 = (const float2*)scores;

    auto mask_tile = [&](int bset, int rt, int cc) {
        __syncthreads();
        if (tid < 64) {
            float4 bj = g_box[bset * NROW + cc * 64 + tid];
            sbx1[tid] = bj.x; sby1[tid] = bj.y; sbx2[tid] = bj.z; sby2[tid] = bj.w;
            sbar[tid] = g_area[bset * NROW + cc * 64 + tid];
        }
        __syncthreads();
        int i = rt * 256 + tid;
        if (i < NROW) {
            float4 bi = g_box[bset * NROW + i];
            float ai = g_area[bset * NROW + i];
            u64 w = 0;
#pragma unroll 4
            for (int k = 0; k < 64; k++)
                if (cc * 64 + k > i && iou_sup(bi, ai, sbx1[k], sby1[k], sbx2[k], sby2[k], sbar[k]))
                    w |= 1ull << k;
            g_mask[((size_t)bset * NROW + i) * WSTRIDE + cc] = w;
        }
    };

    auto scan_emit = [&](int b, int limit, bool force) -> bool {
        int set = (tid >> 6) & 1, lt = tid & 63;
        bool act = tid < 128;
        const u64* M = &g_mask[(size_t)(b * 2 + set) * NROW * WSTRIDE];
        if (tid == 0) { sh_comb = 0; sh_done = 0; sh_cur[0] = 0; sh_cur[1] = 0; }
        __syncthreads();
        int c = 0;
        for (; c < limit; c++) {
            if (act) sh_diag[set][lt] = M[(size_t)(c * 64 + lt) * WSTRIDE + c];
            __syncthreads();
            if (act && lt == 0) {
                u64 cur = sh_cur[set], keep = 0;
                int lim = min(64, K_PRE - c * 64);
                for (int k = 0; k < lim; k++)
                    if (!((cur >> k) & 1ull)) { keep |= 1ull << k; cur |= sh_diag[set][k]; }
                sh_keep[set][c] = keep;
            }
            __syncthreads();
            if (tid == 0) {
                sh_comb += __popcll(sh_keep[0][c] & sh_keep[1][c]);
                if (sh_comb >= K_POST) sh_done = 1;
            }
            if (tid < 2) sh_next[tid] = 0;
            __syncthreads();
            if (sh_done) { c++; break; }
            if (c + 1 < limit) {
                if (act) {
                    u64 acc = 0;
                    for (int r = lt; r < (c + 1) * 64; r += 64)
                        if ((sh_keep[set][r >> 6] >> (r & 63)) & 1ull)
                            acc |= M[(size_t)r * WSTRIDE + (c + 1)];
                    for (int o = 16; o; o >>= 1) acc |= __shfl_xor_sync(0xffffffffu, acc, o);
                    if ((tid & 31) == 0 && acc) atomicOr((unsigned long long*)&sh_next[set], acc);
                }
                __syncthreads();
                if (act && lt == 0) sh_cur[set] = sh_next[set];
                __syncthreads();
            }
        }
        if (!sh_done && !force) return false;
        int chunks = c;
        float* outL = out + (size_t)b * K_POST * 5;
        float* outR = out + (size_t)(B + b) * K_POST * 5;
        for (int i2 = tid; i2 < K_POST * 5; i2 += TPB) {
            float v = (i2 % 5 == 0) ? (float)b : 0.f;
            outL[i2] = v; outR[i2] = v;
        }
        for (int w = tid; w < NWORD; w += TPB)
            sh_cw[w] = (w < chunks) ? (sh_keep[0][w] & sh_keep[1][w]) : 0ull;
        __syncthreads();
        if (tid == 0) {
            int s = 0;
            for (int w = 0; w < NWORD; w++) { sh_pref[w] = s; s += __popcll(sh_cw[w]); }
            sh_nk = s < K_POST ? s : K_POST;
        }
        __syncthreads();
        int nk = sh_nk;
        for (int w = tid; w < NWORD; w += TPB) {
            int rank = sh_pref[w];
            u64 m = sh_cw[w];
            while (m && rank < nk) {
                int k = __ffsll((long long)m) - 1; m &= m - 1;
                int r = w * 64 + k;
                float4 bl = g_box[(b * 2 + 0) * NROW + r];
                float4 br = g_box[(b * 2 + 1) * NROW + r];
                outL[rank * 5 + 1] = bl.x; outL[rank * 5 + 2] = bl.y;
                outL[rank * 5 + 3] = bl.z; outL[rank * 5 + 4] = bl.w;
                outR[rank * 5 + 1] = br.x; outR[rank * 5 + 2] = br.y;
                outR[rank * 5 + 3] = br.z; outR[rank * 5 + 4] = br.w;
                rank++;
            }
        }
        __syncthreads();
        return true;
    };

    // ---- Phase A: conservative compact (s >= CONS_TH) ----
    for (int idx = bid * TPB + tid; idx < total; idx += GRID * TPB) {
        int b = idx / N, i = idx - b * N;
        float s = sc2[idx].y;
        if (s >= CONS_TH) {
            u32 u = score_map(s);
            int q = atomicAdd(&g_scount[b], 1);
            if (q < SCAP)
                g_scand[b * SCAP + q] = ((u64)u << 32) | (u32)(0xFFFFFFFFu - (u32)i);
        }
    }
    gbar();

    // ---- Phase B: validate + exact rank + decode (16 blocks per image) ----
    if (bid == 0 && tid == 0)
        for (int b = 0; b < B; b++) {
            int C2 = g_scount[b];
            if (C2 < K_SPEC || C2 > SCAP) g_full = 1;
        }
    {
        int b = bid >> 4;
        if (b < B) {
            int C2 = min(g_scount[b], SCAP);
            int j0 = (bid & 15) * TPB;
            if (j0 < C2) {
                int C2p = (C2 + 3) & ~3;
                for (int t = tid; t < C2p; t += TPB)
                    sh_tile[t] = (t < C2) ? g_scand[b * SCAP + t] : 0ull;
                __syncthreads();
                int j = j0 + tid;
                if (j < C2) {
                    u64 my = sh_tile[j];
                    int rank = 0;
#pragma unroll 4
                    for (int t = 0; t < C2p; t++) rank += (sh_tile[t] > my) ? 1 : 0;
                    decode_write(b, rank, (u32)(my & 0xFFFFFFFFull), deltas, iminfo, anchors, N);
                }
            }
        }
    }
    gbar();

    // ---- Phase C: speculative IoU mask (top 1024 rows/cols) ----
    int full = *(volatile int*)&g_full;
    if (!full) {
        int ntile = 40 * 2 * B;
        for (int tix = bid; tix < ntile; tix += GRID) {
            int bset = tix / 40, r = tix % 40;
            int rt, cc;
            if (r < 16) { rt = 0; cc = r; }
            else if (r < 28) { rt = 1; cc = 4 + r - 16; }
            else if (r < 36) { rt = 2; cc = 8 + r - 28; }
            else { rt = 3; cc = 12 + r - 36; }
            mask_tile(bset, rt, cc);
        }
    }
    gbar();

    // ---- Phase D: spec scan + emit (blocks 0..B-1) ----
    full = *(volatile int*)&g_full;
    if (!full && bid < B) {
        if (!scan_emit(bid, SPEC_W, false)) {
            if (tid == 0) g_full = 1;
        }
    }
    gbar();

    // ---- Phase E: exact fallback (rare; grid-cooperative) ----
    full = *(volatile int*)&g_full;
    if (full) {
        for (int k = bid * TPB + tid; k < B * 65536; k += GRID * TPB) g_hist[k] = 0;
        gbar();
        for (int idx = bid * TPB + tid; idx < total; idx += GRID * TPB) {
            int b = idx / N;
            u32 u = score_map(sc2[idx].y);
            atomicAdd(&g_hist[(b << 16) + (int)(u >> 16)], 1);
        }
        gbar();
        if (bid < B) {
            int b = bid;
            int* h = &g_hist[b << 16];
            int sum = 0;
            for (int k = 0; k < 256; k++) sum += h[tid * 256 + k];
            sh_part[tid] = sum;
            __syncthreads();
            if (tid == 0) {
                int cum = 0, seg = 255;
                for (; seg > 0; seg--) { if (cum + sh_part[seg] >= K_PRE) break; cum += sh_part[seg]; }
                int bin = seg * 256 + 255, lo = seg * 256;
                for (;; bin--) { int c = h[bin]; if (cum + c >= K_PRE || bin == lo) break; cum += c; }
                g_T16g[b] = bin;
            }
        }
        gbar();
        for (int idx = bid * TPB + tid; idx < total; idx += GRID * TPB) {
            int b = idx / N, i = idx - b * N;
            u32 u = score_map(sc2[idx].y);
            if ((int)(u >> 16) >= g_T16g[b]) {
                int p = atomicAdd(&g_ccount[b], 1);
                if (p < CAP)
                    g_cand[b * CAP + p] = ((u64)u << 32) | (u32)(0xFFFFFFFFu - (u32)i);
            }
        }
        gbar();
        {
            int b = bid >> 6;            // 64 blocks per image covers CAP
            if (b < B) {
                int C = min(g_ccount[b], CAP);
                int j0 = (bid & 63) * TPB;
                if (j0 < C) {
                    int j = j0 + tid;
                    u64 my = (j < C) ? g_cand[b * CAP + j] : 0ull;
                    int rank = 0;
                    for (int c0 = 0; c0 < C; c0 += SCAP) {
                        int nt = min(SCAP, C - c0);
                        int ntp = (nt + 3) & ~3;
                        __syncthreads();
                        for (int t = tid; t < ntp; t += TPB)
                            sh_tile[t] = (t < nt) ? g_cand[b * CAP + c0 + t] : 0ull;
                        __syncthreads();
                        if (j < C) {
#pragma unroll 4
                            for (int t = 0; t < ntp; t++) rank += (sh_tile[t] > my) ? 1 : 0;
                        }
                    }
                    if (j < C && rank < K_PRE)
                        decode_write(b, rank, (u32)(my & 0xFFFFFFFFull), deltas, iminfo, anchors, N);
                }
            }
        }
        gbar();
        {
            const int per = 1152;        // sum_{rt=0..23} (94-4*rt)
            int ntile = per * 2 * B;
            for (int tix = bid; tix < ntile; tix += GRID) {
                int bset = tix / per, r = tix % per;
                int rt = 0, cnt = 94;
                while (r >= cnt) { r -= cnt; rt++; cnt = 94 - 4 * rt; }
                mask_tile(bset, rt, 4 * rt + r);
            }
        }
        gbar();
        if (bid < B) scan_emit(bid, NWORD, true);
        gbar();
    }

    // ---- cleanup for next graph replay ----
    if (bid == 0 && tid == 0) {
        for (int b = 0; b < MAXB; b++) { g_scount[b] = 0; g_ccount[b] = 0; }
        g_full = 0;
    }
}

extern "C" void kernel_launch(void* const* d_in, const int* in_sizes, int n_in,
                              void* d_out, int out_size) {
    const float* scores  = (const float*)d_in[0];
    const float* deltas  = (const float*)d_in[1];
    const float* iminfo  = (const float*)d_in[2];
    const float* anchors = (const float*)d_in[3];
    float* out = (float*)d_out;
    int B = in_sizes[2] / 3;
    int N = in_sizes[3] / 4;

    k_all<<<GRID, TPB>>>(out, scores, deltas, iminfo, anchors, B, N);
}

// round 12
// speedup vs baseline: 5.6158x; 1.3759x over previous
#include <cuda_runtime.h>
#include <cstdint>
#include <math.h>

typedef unsigned long long u64;
typedef unsigned int u32;

#define K_PRE 6000
#define K_SPEC 1024
#define K_POST 300
#define NMS_TH 0.7f
#define CONS_TH 0.994f
#define NROW 6016
#define NWORD 94
#define WSTRIDE 96
#define MAXB 2
#define CAP 16384
#define SCAP 2048
#define SPEC_W 16
#define GRID 148
#define TPB 256

// ---------- persistent device scratch (self-cleaning across graph replays) ----------
__device__ int    g_hist[MAXB * 65536];
__device__ int    g_T16g[MAXB];
__device__ int    g_ccount[MAXB], g_scount[MAXB];   // zeroed at end of kernel
__device__ u64    g_cand[MAXB * CAP];
__device__ u64    g_scand[MAXB * SCAP];
__device__ float4 g_box[2 * MAXB * NROW];
__device__ float  g_area[2 * MAXB * NROW];
__device__ u64    g_mask[(size_t)2 * MAXB * NROW * WSTRIDE];
__device__ int    g_full;                            // reset at end of kernel
__device__ u32    g_bcnt;                            // barrier arrival count (self-resets)
__device__ volatile u32 g_bgen;                      // barrier generation (monotonic)

__device__ __forceinline__ void gbar() {
    __syncthreads();
    if (threadIdx.x == 0) {
        u32 gen = g_bgen;
        __threadfence();
        if (atomicAdd(&g_bcnt, 1) == GRID - 1) {
            g_bcnt = 0;
            __threadfence();
            g_bgen = gen + 1;
        } else {
            while (g_bgen == gen) { }
        }
        __threadfence();
    }
    __syncthreads();
}

__device__ __forceinline__ u32 score_map(float s) {
    u32 u = __float_as_uint(s);
    return (u & 0x80000000u) ? ~u : (u | 0x80000000u);
}

__device__ __forceinline__ bool iou_sup(float4 bi, float ai,
                                        float x1, float y1, float x2, float y2, float ar) {
    float xx1 = fmaxf(bi.x, x1), yy1 = fmaxf(bi.y, y1);
    float xx2 = fminf(bi.z, x2), yy2 = fminf(bi.w, y2);
    float ow = xx2 - xx1 + 1.0f, oh = yy2 - yy1 + 1.0f;
    if (!(ow > 0.0f && oh > 0.0f)) return false;
    float inter = ow * oh;
    float uni = ai + ar - inter;
    float p = NMS_TH * uni;
    bool sup = inter > p;
    if (fabsf(inter - p) <= 1e-5f * uni)     // borderline: exact IEEE decision
        sup = __fdiv_rn(inter, uni) > NMS_TH;
    return sup;
}

__device__ __forceinline__ void decode_write(int b, int rank, u32 lo,
        const float* __restrict__ deltas, const float* __restrict__ iminfo,
        const float* __restrict__ anchors, int N) {
    int i = (int)(0xFFFFFFFFu - lo);
    const float* a = anchors + (size_t)i * 4;
    float w = a[2] - a[0] + 1.0f;
    float h = a[3] - a[1] + 1.0f;
    float cx = a[0] + 0.5f * w;
    float cy = a[1] + 0.5f * h;
    const float* d = deltas + ((size_t)b * N + i) * 6;
    float Hm1 = iminfo[b * 3 + 0] - 1.0f;
    float Wm1 = iminfo[b * 3 + 1] - 1.0f;
    float eh = (float)exp((double)d[3]) * h;   // accurate exp (fast-math safe)
    float pcy = d[1] * h + cy;
    float y1 = fminf(fmaxf(pcy - 0.5f * eh, 0.f), Hm1);
    float y2 = fminf(fmaxf(pcy + 0.5f * eh, 0.f), Hm1);
    {
        float pcx = d[0] * w + cx;
        float pw = (float)exp((double)d[2]) * w;
        float x1 = fminf(fmaxf(pcx - 0.5f * pw, 0.f), Wm1);
        float x2 = fminf(fmaxf(pcx + 0.5f * pw, 0.f), Wm1);
        g_box[(b * 2 + 0) * NROW + rank] = make_float4(x1, y1, x2, y2);
        g_area[(b * 2 + 0) * NROW + rank] = (x2 - x1 + 1.0f) * (y2 - y1 + 1.0f);
    }
    {
        float pcx = d[4] * w + cx;
        float pw = (float)exp((double)d[5]) * w;
        float x1 = fminf(fmaxf(pcx - 0.5f * pw, 0.f), Wm1);
        float x2 = fminf(fmaxf(pcx + 0.5f * pw, 0.f), Wm1);
        g_box[(b * 2 + 1) * NROW + rank] = make_float4(x1, y1, x2, y2);
        g_area[(b * 2 + 1) * NROW + rank] = (x2 - x1 + 1.0f) * (y2 - y1 + 1.0f);
    }
}

union ShU {
    u64 tile[SCAP];                                   // 16KB rank tile
    struct { u64 diag[2][SPEC_W][64]; u64 col[2][K_SPEC]; } scan;   // 16+16 KB
};

extern "C" __global__ void __launch_bounds__(TPB) k_all(
    float* __restrict__ out,
    const float* __restrict__ scores,
    const float* __restrict__ deltas,
    const float* __restrict__ iminfo,
    const float* __restrict__ anchors,
    int B, int N)
{
    __shared__ ShU   shu;
    __shared__ u64   sh_nz[2][SPEC_W];
    __shared__ float sbx1[64], sby1[64], sbx2[64], sby2[64], sbar[64];
    __shared__ u64   sh_keep[2][NWORD];
    __shared__ u64   sh_diag[2][64];                  // fallback scan only
    __shared__ u64   sh_next[2], sh_cur[2];
    __shared__ int   sh_comb, sh_done, sh_nk;
    __shared__ u64   sh_cw[NWORD];
    __shared__ int   sh_pref[NWORD];
    __shared__ int   sh_part[256];

    int bid = blockIdx.x, tid = threadIdx.x;
    int total = B * N;
    const float2* sc2 = (const float2*)scores;

    auto mask_tile = [&](int bset, int rt, int cc) {
        __syncthreads();
        if (tid < 64) {
            float4 bj = g_box[bset * NROW + cc * 64 + tid];
            sbx1[tid] = bj.x; sby1[tid] = bj.y; sbx2[tid] = bj.z; sby2[tid] = bj.w;
            sbar[tid] = g_area[bset * NROW + cc * 64 + tid];
        }
        __syncthreads();
        int i = rt * 256 + tid;
        if (i < NROW) {
            float4 bi = g_box[bset * NROW + i];
            float ai = g_area[bset * NROW + i];
            u64 w = 0;
#pragma unroll 4
            for (int k = 0; k < 64; k++)
                if (cc * 64 + k > i && iou_sup(bi, ai, sbx1[k], sby1[k], sbx2[k], sby2[k], sbar[k]))
                    w |= 1ull << k;
            g_mask[((size_t)bset * NROW + i) * WSTRIDE + cc] = w;
        }
    };

    auto emit = [&](int b, int chunks) {
        float* outL = out + (size_t)b * K_POST * 5;
        float* outR = out + (size_t)(B + b) * K_POST * 5;
        for (int i2 = tid; i2 < K_POST * 5; i2 += TPB) {
            float v = (i2 % 5 == 0) ? (float)b : 0.f;
            outL[i2] = v; outR[i2] = v;
        }
        for (int w = tid; w < NWORD; w += TPB)
            sh_cw[w] = (w < chunks) ? (sh_keep[0][w] & sh_keep[1][w]) : 0ull;
        __syncthreads();
        if (tid == 0) {
            int s = 0;
            for (int w = 0; w < NWORD; w++) { sh_pref[w] = s; s += __popcll(sh_cw[w]); }
            sh_nk = s < K_POST ? s : K_POST;
        }
        __syncthreads();
        int nk = sh_nk;
        for (int w = tid; w < NWORD; w += TPB) {
            int rank = sh_pref[w];
            u64 m = sh_cw[w];
            while (m && rank < nk) {
                int k = __ffsll((long long)m) - 1; m &= m - 1;
                int r = w * 64 + k;
                float4 bl = g_box[(b * 2 + 0) * NROW + r];
                float4 br = g_box[(b * 2 + 1) * NROW + r];
                outL[rank * 5 + 1] = bl.x; outL[rank * 5 + 2] = bl.y;
                outL[rank * 5 + 3] = bl.z; outL[rank * 5 + 4] = bl.w;
                outR[rank * 5 + 1] = br.x; outR[rank * 5 + 2] = br.y;
                outR[rank * 5 + 3] = br.z; outR[rank * 5 + 4] = br.w;
                rank++;
            }
        }
        __syncthreads();
    };

    // fallback scan (global mask reads, full NWORD, always emits)
    auto scan_emit_full = [&](int b) {
        int set = (tid >> 6) & 1, lt = tid & 63;
        bool act = tid < 128;
        const u64* M = &g_mask[(size_t)(b * 2 + set) * NROW * WSTRIDE];
        if (tid == 0) { sh_comb = 0; sh_done = 0; sh_cur[0] = 0; sh_cur[1] = 0; }
        __syncthreads();
        int c = 0;
        for (; c < NWORD; c++) {
            if (act) sh_diag[set][lt] = M[(size_t)(c * 64 + lt) * WSTRIDE + c];
            __syncthreads();
            if (act && lt == 0) {
                u64 cur = sh_cur[set], keep = 0;
                int lim = min(64, K_PRE - c * 64);
                for (int k = 0; k < lim; k++)
                    if (!((cur >> k) & 1ull)) { keep |= 1ull << k; cur |= sh_diag[set][k]; }
                sh_keep[set][c] = keep;
            }
            __syncthreads();
            if (tid == 0) {
                sh_comb += __popcll(sh_keep[0][c] & sh_keep[1][c]);
                if (sh_comb >= K_POST) sh_done = 1;
            }
            if (tid < 2) sh_next[tid] = 0;
            __syncthreads();
            if (sh_done) { c++; break; }
            if (c + 1 < NWORD) {
                if (act) {
                    u64 acc = 0;
                    for (int r = lt; r < (c + 1) * 64; r += 64)
                        if ((sh_keep[set][r >> 6] >> (r & 63)) & 1ull)
                            acc |= M[(size_t)r * WSTRIDE + (c + 1)];
                    for (int o = 16; o; o >>= 1) acc |= __shfl_xor_sync(0xffffffffu, acc, o);
                    if ((tid & 31) == 0 && acc) atomicOr((unsigned long long*)&sh_next[set], acc);
                }
                __syncthreads();
                if (act && lt == 0) sh_cur[set] = sh_next[set];
                __syncthreads();
            }
        }
        emit(b, c);
    };

    // ---- Phase A: conservative compact (s >= CONS_TH), vectorized ----
    for (int b = 0; b < B; b++) {
        const float4* s4 = (const float4*)(scores + (size_t)b * N * 2);
        int n4 = N >> 1;
        for (int j = bid * TPB + tid; j < n4; j += GRID * TPB) {
            float4 v = s4[j];
            if (v.y >= CONS_TH) {
                u32 u = score_map(v.y);
                int q = atomicAdd(&g_scount[b], 1);
                if (q < SCAP)
                    g_scand[b * SCAP + q] = ((u64)u << 32) | (u32)(0xFFFFFFFFu - (u32)(2 * j));
            }
            if (v.w >= CONS_TH) {
                u32 u = score_map(v.w);
                int q = atomicAdd(&g_scount[b], 1);
                if (q < SCAP)
                    g_scand[b * SCAP + q] = ((u64)u << 32) | (u32)(0xFFFFFFFFu - (u32)(2 * j + 1));
            }
        }
        if ((N & 1) && bid == 0 && tid == 0) {
            float s = sc2[(size_t)b * N + (N - 1)].y;
            if (s >= CONS_TH) {
                u32 u = score_map(s);
                int q = atomicAdd(&g_scount[b], 1);
                if (q < SCAP)
                    g_scand[b * SCAP + q] = ((u64)u << 32) | (u32)(0xFFFFFFFFu - (u32)(N - 1));
            }
        }
    }
    gbar();

    // ---- Phase B: validate + exact rank + decode (8 blocks per image) ----
    if (bid == 0 && tid == 0)
        for (int b = 0; b < B; b++) {
            int C2 = g_scount[b];
            if (C2 < K_SPEC || C2 > SCAP) g_full = 1;
        }
    {
        int b = bid >> 3;
        if (b < B) {
            int C2 = min(g_scount[b], SCAP);
            int j0 = (bid & 7) * TPB;
            if (j0 < C2) {
                int C2p = (C2 + 7) & ~7;
                for (int t = tid; t < C2p; t += TPB)
                    shu.tile[t] = (t < C2) ? g_scand[b * SCAP + t] : 0ull;
                __syncthreads();
                int j = j0 + tid;
                if (j < C2) {
                    u64 my = shu.tile[j];
                    int rank = 0;
                    const ulonglong2* t2 = (const ulonglong2*)shu.tile;
                    int n2 = C2p >> 1;
#pragma unroll 8
                    for (int t = 0; t < n2; t++) {
                        ulonglong2 v = t2[t];
                        rank += (v.x > my) ? 1 : 0;
                        rank += (v.y > my) ? 1 : 0;
                    }
                    decode_write(b, rank, (u32)(my & 0xFFFFFFFFull), deltas, iminfo, anchors, N);
                }
            }
        }
    }
    gbar();

    // ---- Phase C: speculative IoU mask (top 1024 rows/cols) ----
    int full = *(volatile int*)&g_full;
    if (!full) {
        int ntile = 40 * 2 * B;
        for (int tix = bid; tix < ntile; tix += GRID) {
            int bset = tix / 40, r = tix % 40;
            int rt, cc;
            if (r < 16) { rt = 0; cc = r; }
            else if (r < 28) { rt = 1; cc = 4 + r - 16; }
            else if (r < 36) { rt = 2; cc = 8 + r - 28; }
            else { rt = 3; cc = 12 + r - 36; }
            mask_tile(bset, rt, cc);
        }
    }
    gbar();

    // ---- Phase D: spec scan (smem-resident diagonals, nz-pruned chain, col prefetch) ----
    full = *(volatile int*)&g_full;
    if (!full && bid < B) {
        int b = bid;
        int set = (tid >> 6) & 1;       // warps 0-1/4-5 -> set0, 2-3/6-7 -> set1
        int lt = tid & 63;
        const u64* Ms = &g_mask[(size_t)(b * 2 + set) * NROW * WSTRIDE];
        if (tid < 2 * SPEC_W) ((u64*)sh_nz)[tid] = 0;
        if (tid == 0) { sh_comb = 0; sh_done = 0; sh_cur[0] = 0; sh_cur[1] = 0; }
        __syncthreads();
        for (int x = tid; x < 2 * SPEC_W * 64; x += TPB) {
            int s = x >> 10;
            int c = (x >> 6) & (SPEC_W - 1);
            int r = x & 63;
            const u64* M = &g_mask[(size_t)(b * 2 + s) * NROW * WSTRIDE];
            u64 v = M[(size_t)(c * 64 + r) * WSTRIDE + c];
            shu.scan.diag[s][c][r] = v;
            if (v) atomicOr((unsigned long long*)&sh_nz[s][c], 1ull << r);
        }
        __syncthreads();
        int c = 0;
        for (; c < SPEC_W; c++) {
            if (tid < 128) {
                if (lt == 0) {          // serial chain, nz-pruned, smem-only
                    u64 cur = sh_cur[set];
                    u64 m = sh_nz[set][c] & ~cur;
                    while (m) {
                        int k = __ffsll((long long)m) - 1;
                        if (!((cur >> k) & 1ull)) cur |= shu.scan.diag[set][c][k];
                        m &= m - 1;
                        m &= ~cur;
                    }
                    sh_keep[set][c] = ~cur;
                }
            } else if (c + 1 < SPEC_W) { // warps 4-7: prefetch next column concurrently
                int rows = (c + 1) * 64;
                for (int r = lt; r < rows; r += 64)
                    shu.scan.col[set][r] = Ms[(size_t)r * WSTRIDE + (c + 1)];
            }
            __syncthreads();
            if (tid == 0) {
                sh_comb += __popcll(sh_keep[0][c] & sh_keep[1][c]);
                if (sh_comb >= K_POST) sh_done = 1;
            }
            if (tid < 2) sh_next[tid] = 0;
            __syncthreads();
            if (sh_done) { c++; break; }
            if (c + 1 < SPEC_W) {
                if (tid < 128) {
                    int rows = (c + 1) * 64;
                    u64 acc = 0;
                    for (int r = lt; r < rows; r += 64)
                        if ((sh_keep[set][r >> 6] >> (r & 63)) & 1ull)
                            acc |= shu.scan.col[set][r];
                    for (int o = 16; o; o >>= 1) acc |= __shfl_xor_sync(0xffffffffu, acc, o);
                    if ((tid & 31) == 0 && acc) atomicOr((unsigned long long*)&sh_next[set], acc);
                }
                __syncthreads();
                if (tid < 128 && lt == 0) sh_cur[set] = sh_next[set];
                __syncthreads();
            }
        }
        if (!sh_done) { if (tid == 0) g_full = 1; }
        else emit(b, c);
    }
    gbar();

    // ---- Phase E: exact fallback (rare; grid-cooperative) ----
    full = *(volatile int*)&g_full;
    if (full) {
        for (int k = bid * TPB + tid; k < B * 65536; k += GRID * TPB) g_hist[k] = 0;
        gbar();
        for (int idx = bid * TPB + tid; idx < total; idx += GRID * TPB) {
            int b = idx / N;
            u32 u = score_map(sc2[idx].y);
            atomicAdd(&g_hist[(b << 16) + (int)(u >> 16)], 1);
        }
        gbar();
        if (bid < B) {
            int b = bid;
            int* h = &g_hist[b << 16];
            int sum = 0;
            for (int k = 0; k < 256; k++) sum += h[tid * 256 + k];
            sh_part[tid] = sum;
            __syncthreads();
            if (tid == 0) {
                int cum = 0, seg = 255;
                for (; seg > 0; seg--) { if (cum + sh_part[seg] >= K_PRE) break; cum += sh_part[seg]; }
                int bin = seg * 256 + 255, lo = seg * 256;
                for (;; bin--) { int cc = h[bin]; if (cum + cc >= K_PRE || bin == lo) break; cum += cc; }
                g_T16g[b] = bin;
            }
        }
        gbar();
        for (int idx = bid * TPB + tid; idx < total; idx += GRID * TPB) {
            int b = idx / N, i = idx - b * N;
            u32 u = score_map(sc2[idx].y);
            if ((int)(u >> 16) >= g_T16g[b]) {
                int p = atomicAdd(&g_ccount[b], 1);
                if (p < CAP)
                    g_cand[b * CAP + p] = ((u64)u << 32) | (u32)(0xFFFFFFFFu - (u32)i);
            }
        }
        gbar();
        {
            int b = bid >> 6;            // 64 blocks per image covers CAP
            if (b < B) {
                int C = min(g_ccount[b], CAP);
                int j0 = (bid & 63) * TPB;
                if (j0 < C) {
                    int j = j0 + tid;
                    u64 my = (j < C) ? g_cand[b * CAP + j] : 0ull;
                    int rank = 0;
                    for (int c0 = 0; c0 < C; c0 += SCAP) {
                        int nt = min(SCAP, C - c0);
                        int ntp = (nt + 3) & ~3;
                        __syncthreads();
                        for (int t = tid; t < ntp; t += TPB)
                            shu.tile[t] = (t < nt) ? g_cand[b * CAP + c0 + t] : 0ull;
                        __syncthreads();
                        if (j < C) {
#pragma unroll 4
                            for (int t = 0; t < ntp; t++) rank += (shu.tile[t] > my) ? 1 : 0;
                        }
                    }
                    if (j < C && rank < K_PRE)
                        decode_write(b, rank, (u32)(my & 0xFFFFFFFFull), deltas, iminfo, anchors, N);
                }
            }
        }
        gbar();
        {
            const int per = 1152;        // sum_{rt=0..23} (94-4*rt)
            int ntile = per * 2 * B;
            for (int tix = bid; tix < ntile; tix += GRID) {
                int bset = tix / per, r = tix % per;
                int rt = 0, cnt = 94;
                while (r >= cnt) { r -= cnt; rt++; cnt = 94 - 4 * rt; }
                mask_tile(bset, rt, 4 * rt + r);
            }
        }
        gbar();
        if (bid < B) scan_emit_full(bid);
        gbar();
    }

    // ---- cleanup for next graph replay ----
    if (bid == 0 && tid == 0) {
        for (int b = 0; b < MAXB; b++) { g_scount[b] = 0; g_ccount[b] = 0; }
        g_full = 0;
    }
}

extern "C" void kernel_launch(void* const* d_in, const int* in_sizes, int n_in,
                              void* d_out, int out_size) {
    const float* scores  = (const float*)d_in[0];
    const float* deltas  = (const float*)d_in[1];
    const float* iminfo  = (const float*)d_in[2];
    const float* anchors = (const float*)d_in[3];
    float* out = (float*)d_out;
    int B = in_sizes[2] / 3;
    int N = in_sizes[3] / 4;

    k_all<<<GRID, TPB>>>(out, scores, deltas, iminfo, anchors, B, N);
}

// round 15
// speedup vs baseline: 5.7250x; 1.0194x over previous
#include <cuda_runtime.h>
#include <cstdint>
#include <math.h>

typedef unsigned long long u64;
typedef unsigned int u32;

#define K_PRE 6000
#define K_SPEC 640
#define K_POST 300
#define NMS_TH 0.7f
#define CONS_TH 0.996f
#define NROW 6016
#define NWORD 94
#define WSTRIDE 96
#define MAXB 2
#define CAP 16384
#define SCAP 2048
#define SPEC_W 10
#define GRID 148
#define TPB 512

// ---------- persistent device scratch (self-cleaning across graph replays) ----------
__device__ int    g_hist[MAXB * 65536];
__device__ int    g_T16g[MAXB];
__device__ int    g_ccount[MAXB], g_scount[MAXB];   // zeroed at end of kernel
__device__ u64    g_cand[MAXB * CAP];
__device__ u64    g_scand[MAXB * SCAP];
__device__ float4 g_box[2 * MAXB * NROW];
__device__ float  g_area[2 * MAXB * NROW];
__device__ u64    g_mask[(size_t)2 * MAXB * NROW * WSTRIDE];
__device__ int    g_full;                            // reset at end of kernel
__device__ u32    g_bcnt;                            // barrier arrival count (self-resets)
__device__ volatile u32 g_bgen;                      // barrier generation (monotonic)

__device__ __forceinline__ void gbar() {
    __syncthreads();
    if (threadIdx.x == 0) {
        u32 gen = g_bgen;
        __threadfence();
        if (atomicAdd(&g_bcnt, 1) == GRID - 1) {
            g_bcnt = 0;
            __threadfence();
            g_bgen = gen + 1;
        } else {
            while (g_bgen == gen) { }
        }
        __threadfence();
    }
    __syncthreads();
}

__device__ __forceinline__ u32 score_map(float s) {
    u32 u = __float_as_uint(s);
    return (u & 0x80000000u) ? ~u : (u | 0x80000000u);
}

__device__ __forceinline__ bool iou_sup(float4 bi, float ai,
                                        float x1, float y1, float x2, float y2, float ar) {
    float xx1 = fmaxf(bi.x, x1), yy1 = fmaxf(bi.y, y1);
    float xx2 = fminf(bi.z, x2), yy2 = fminf(bi.w, y2);
    float ow = xx2 - xx1 + 1.0f, oh = yy2 - yy1 + 1.0f;
    if (!(ow > 0.0f && oh > 0.0f)) return false;
    float inter = ow * oh;
    float uni = ai + ar - inter;
    float p = NMS_TH * uni;
    bool sup = inter > p;
    if (fabsf(inter - p) <= 1e-5f * uni)     // borderline: exact IEEE decision
        sup = __fdiv_rn(inter, uni) > NMS_TH;
    return sup;
}

__device__ __forceinline__ void decode_write(int b, int rank, u32 lo,
        const float* __restrict__ deltas, const float* __restrict__ iminfo,
        const float* __restrict__ anchors, int N) {
    int i = (int)(0xFFFFFFFFu - lo);
    const float* a = anchors + (size_t)i * 4;
    float w = a[2] - a[0] + 1.0f;
    float h = a[3] - a[1] + 1.0f;
    float cx = a[0] + 0.5f * w;
    float cy = a[1] + 0.5f * h;
    const float* d = deltas + ((size_t)b * N + i) * 6;
    float Hm1 = iminfo[b * 3 + 0] - 1.0f;
    float Wm1 = iminfo[b * 3 + 1] - 1.0f;
    float eh = (float)exp((double)d[3]) * h;   // accurate exp (fast-math safe)
    float pcy = d[1] * h + cy;
    float y1 = fminf(fmaxf(pcy - 0.5f * eh, 0.f), Hm1);
    float y2 = fminf(fmaxf(pcy + 0.5f * eh, 0.f), Hm1);
    {
        float pcx = d[0] * w + cx;
        float pw = (float)exp((double)d[2]) * w;
        float x1 = fminf(fmaxf(pcx - 0.5f * pw, 0.f), Wm1);
        float x2 = fminf(fmaxf(pcx + 0.5f * pw, 0.f), Wm1);
        g_box[(b * 2 + 0) * NROW + rank] = make_float4(x1, y1, x2, y2);
        g_area[(b * 2 + 0) * NROW + rank] = (x2 - x1 + 1.0f) * (y2 - y1 + 1.0f);
    }
    {
        float pcx = d[4] * w + cx;
        float pw = (float)exp((double)d[5]) * w;
        float x1 = fminf(fmaxf(pcx - 0.5f * pw, 0.f), Wm1);
        float x2 = fminf(fmaxf(pcx + 0.5f * pw, 0.f), Wm1);
        g_box[(b * 2 + 1) * NROW + rank] = make_float4(x1, y1, x2, y2);
        g_area[(b * 2 + 1) * NROW + rank] = (x2 - x1 + 1.0f) * (y2 - y1 + 1.0f);
    }
}

union ShU {
    u64 tile[SCAP];                                                  // 16KB rank tile
    struct { u64 diag[2][SPEC_W][64]; u64 col[2][K_SPEC]; } scan;    // 10+10 KB
};

extern "C" __global__ void __launch_bounds__(TPB) k_all(
    float* __restrict__ out,
    const float* __restrict__ scores,
    const float* __restrict__ deltas,
    const float* __restrict__ iminfo,
    const float* __restrict__ anchors,
    int B, int N)
{
    __shared__ ShU   shu;
    __shared__ u64   sh_nz[2][SPEC_W];
    __shared__ float sbx1[64], sby1[64], sbx2[64], sby2[64], sbar[64];
    __shared__ u64   sh_keep[2][NWORD];
    __shared__ u64   sh_diag[2][64];                  // fallback scan only
    __shared__ u64   sh_next[2], sh_cur[2];
    __shared__ int   sh_comb, sh_done, sh_nk;
    __shared__ u64   sh_cw[NWORD];
    __shared__ int   sh_pref[NWORD];
    __shared__ int   sh_part[256];

    int bid = blockIdx.x, tid = threadIdx.x;
    int total = B * N;
    const float2* sc2 = (const float2*)scores;

    // 512-row x 64-col mask tile
    auto mask_tile = [&](int bset, int rt, int cc) {
        __syncthreads();
        if (tid < 64) {
            float4 bj = g_box[bset * NROW + cc * 64 + tid];
            sbx1[tid] = bj.x; sby1[tid] = bj.y; sbx2[tid] = bj.z; sby2[tid] = bj.w;
            sbar[tid] = g_area[bset * NROW + cc * 64 + tid];
        }
        __syncthreads();
        int i = rt * TPB + tid;
        if (i < NROW) {
            float4 bi = g_box[bset * NROW + i];
            float ai = g_area[bset * NROW + i];
            u64 w = 0;
#pragma unroll 4
            for (int k = 0; k < 64; k++)
                if (cc * 64 + k > i && iou_sup(bi, ai, sbx1[k], sby1[k], sbx2[k], sby2[k], sbar[k]))
                    w |= 1ull << k;
            g_mask[((size_t)bset * NROW + i) * WSTRIDE + cc] = w;
        }
    };

    auto emit = [&](int b, int chunks) {
        float* outL = out + (size_t)b * K_POST * 5;
        float* outR = out + (size_t)(B + b) * K_POST * 5;
        for (int i2 = tid; i2 < K_POST * 5; i2 += TPB) {
            float v = (i2 % 5 == 0) ? (float)b : 0.f;
            outL[i2] = v; outR[i2] = v;
        }
        for (int w = tid; w < NWORD; w += TPB)
            sh_cw[w] = (w < chunks) ? (sh_keep[0][w] & sh_keep[1][w]) : 0ull;
        __syncthreads();
        if (tid == 0) {
            int s = 0;
            for (int w = 0; w < NWORD; w++) { sh_pref[w] = s; s += __popcll(sh_cw[w]); }
            sh_nk = s < K_POST ? s : K_POST;
        }
        __syncthreads();
        int nk = sh_nk;
        for (int w = tid; w < NWORD; w += TPB) {
            int rank = sh_pref[w];
            u64 m = sh_cw[w];
            while (m && rank < nk) {
                int k = __ffsll((long long)m) - 1; m &= m - 1;
                int r = w * 64 + k;
                float4 bl = g_box[(b * 2 + 0) * NROW + r];
                float4 br = g_box[(b * 2 + 1) * NROW + r];
                outL[rank * 5 + 1] = bl.x; outL[rank * 5 + 2] = bl.y;
                outL[rank * 5 + 3] = bl.z; outL[rank * 5 + 4] = bl.w;
                outR[rank * 5 + 1] = br.x; outR[rank * 5 + 2] = br.y;
                outR[rank * 5 + 3] = br.z; outR[rank * 5 + 4] = br.w;
                rank++;
            }
        }
        __syncthreads();
    };

    // fallback scan (global mask reads, full NWORD, always emits)
    auto scan_emit_full = [&](int b) {
        int set = (tid >> 6) & 1, lt = tid & 63;
        bool act = tid < 128;
        const u64* M = &g_mask[(size_t)(b * 2 + set) * NROW * WSTRIDE];
        if (tid == 0) { sh_comb = 0; sh_done = 0; sh_cur[0] = 0; sh_cur[1] = 0; }
        __syncthreads();
        int c = 0;
        for (; c < NWORD; c++) {
            if (act) sh_diag[set][lt] = M[(size_t)(c * 64 + lt) * WSTRIDE + c];
            __syncthreads();
            if (act && lt == 0) {
                u64 cur = sh_cur[set], keep = 0;
                int lim = min(64, K_PRE - c * 64);
                for (int k = 0; k < lim; k++)
                    if (!((cur >> k) & 1ull)) { keep |= 1ull << k; cur |= sh_diag[set][k]; }
                sh_keep[set][c] = keep;
            }
            __syncthreads();
            if (tid == 0) {
                sh_comb += __popcll(sh_keep[0][c] & sh_keep[1][c]);
                if (sh_comb >= K_POST) sh_done = 1;
            }
            if (tid < 2) sh_next[tid] = 0;
            __syncthreads();
            if (sh_done) { c++; break; }
            if (c + 1 < NWORD) {
                if (act) {
                    u64 acc = 0;
                    for (int r = lt; r < (c + 1) * 64; r += 64)
                        if ((sh_keep[set][r >> 6] >> (r & 63)) & 1ull)
                            acc |= M[(size_t)r * WSTRIDE + (c + 1)];
                    for (int o = 16; o; o >>= 1) acc |= __shfl_xor_sync(0xffffffffu, acc, o);
                    if ((tid & 31) == 0 && acc) atomicOr((unsigned long long*)&sh_next[set], acc);
                }
                __syncthreads();
                if (act && lt == 0) sh_cur[set] = sh_next[set];
                __syncthreads();
            }
        }
        emit(b, c);
    };

    // ---- Phase A: conservative compact (s >= CONS_TH), vectorized ----
    for (int b = 0; b < B; b++) {
        const float4* s4 = (const float4*)(scores + (size_t)b * N * 2);
        int n4 = N >> 1;
        for (int j = bid * TPB + tid; j < n4; j += GRID * TPB) {
            float4 v = s4[j];
            if (v.y >= CONS_TH) {
                u32 u = score_map(v.y);
                int q = atomicAdd(&g_scount[b], 1);
                if (q < SCAP)
                    g_scand[b * SCAP + q] = ((u64)u << 32) | (u32)(0xFFFFFFFFu - (u32)(2 * j));
            }
            if (v.w >= CONS_TH) {
                u32 u = score_map(v.w);
                int q = atomicAdd(&g_scount[b], 1);
                if (q < SCAP)
                    g_scand[b * SCAP + q] = ((u64)u << 32) | (u32)(0xFFFFFFFFu - (u32)(2 * j + 1));
            }
        }
        if ((N & 1) && bid == 0 && tid == 0) {
            float s = sc2[(size_t)b * N + (N - 1)].y;
            if (s >= CONS_TH) {
                u32 u = score_map(s);
                int q = atomicAdd(&g_scount[b], 1);
                if (q < SCAP)
                    g_scand[b * SCAP + q] = ((u64)u << 32) | (u32)(0xFFFFFFFFu - (u32)(N - 1));
            }
        }
    }
    gbar();

    // ---- Phase B: validate + exact rank + decode (4 blocks per image) ----
    if (bid == 0 && tid == 0)
        for (int b = 0; b < B; b++) {
            int C2 = g_scount[b];
            if (C2 < K_SPEC || C2 > SCAP) g_full = 1;
        }
    {
        int b = bid >> 2;
        if (b < B) {
            int C2 = min(g_scount[b], SCAP);
            int j0 = (bid & 3) * TPB;
            if (j0 < C2) {
                int C2p = (C2 + 7) & ~7;
                for (int t = tid; t < C2p; t += TPB)
                    shu.tile[t] = (t < C2) ? g_scand[b * SCAP + t] : 0ull;
                __syncthreads();
                int j = j0 + tid;
                if (j < C2) {
                    u64 my = shu.tile[j];
                    int rank = 0;
                    const ulonglong2* t2 = (const ulonglong2*)shu.tile;
                    int n2 = C2p >> 1;
#pragma unroll 8
                    for (int t = 0; t < n2; t++) {
                        ulonglong2 v = t2[t];
                        rank += (v.x > my) ? 1 : 0;
                        rank += (v.y > my) ? 1 : 0;
                    }
                    decode_write(b, rank, (u32)(my & 0xFFFFFFFFull), deltas, iminfo, anchors, N);
                }
            }
        }
    }
    gbar();

    // ---- Phase C: speculative IoU mask (top SPEC_W*64 rows/cols) ----
    int full = *(volatile int*)&g_full;
    if (!full) {
        // per set: rt=0 -> cc 0..9 (10 tiles); rt=1 -> cc 8..9 (2 tiles)  => 12/set
        int ntile = 12 * 2 * B;
        for (int tix = bid; tix < ntile; tix += GRID) {
            int bset = tix / 12, r = tix % 12;
            int rt, cc;
            if (r < SPEC_W) { rt = 0; cc = r; }
            else { rt = 1; cc = 8 + (r - SPEC_W); }
            mask_tile(bset, rt, cc);
        }
    }
    gbar();

    // ---- Phase D: spec scan (smem diagonals, nz-pruned chain, col prefetch) ----
    full = *(volatile int*)&g_full;
    if (!full && bid < B) {
        int b = bid;
        int set = (tid >> 6) & 1;
        int lt = tid & 63;
        const u64* Ms = &g_mask[(size_t)(b * 2 + set) * NROW * WSTRIDE];
        if (tid < 2 * SPEC_W) ((u64*)sh_nz)[tid] = 0;
        if (tid == 0) { sh_comb = 0; sh_done = 0; sh_cur[0] = 0; sh_cur[1] = 0; }
        __syncthreads();
        for (int x = tid; x < 2 * SPEC_W * 64; x += TPB) {
            int s = (x >= SPEC_W * 64) ? 1 : 0;
            int y = x - s * SPEC_W * 64;
            int c = y >> 6;
            int r = y & 63;
            const u64* M = &g_mask[(size_t)(b * 2 + s) * NROW * WSTRIDE];
            u64 v = M[(size_t)(c * 64 + r) * WSTRIDE + c];
            shu.scan.diag[s][c][r] = v;
            if (v) atomicOr((unsigned long long*)&sh_nz[s][c], 1ull << r);
        }
        __syncthreads();
        int c = 0;
        for (; c < SPEC_W; c++) {
            if (tid < 128) {
                if (lt == 0) {          // serial chain, nz-pruned, smem-only
                    u64 cur = sh_cur[set];
                    u64 m = sh_nz[set][c] & ~cur;
                    while (m) {
                        int k = __ffsll((long long)m) - 1;
                        if (!((cur >> k) & 1ull)) cur |= shu.scan.diag[set][c][k];
                        m &= m - 1;
                        m &= ~cur;
                    }
                    sh_keep[set][c] = ~cur;
                }
            } else if (tid < 256 && c + 1 < SPEC_W) {   // warps 4-7: prefetch next column
                int rows = (c + 1) * 64;
                for (int r = lt; r < rows; r += 64)
                    shu.scan.col[set][r] = Ms[(size_t)r * WSTRIDE + (c + 1)];
            }
            __syncthreads();
            if (tid == 0) {
                sh_comb += __popcll(sh_keep[0][c] & sh_keep[1][c]);
                if (sh_comb >= K_POST) sh_done = 1;
            }
            if (tid < 2) sh_next[tid] = 0;
            __syncthreads();
            if (sh_done) { c++; break; }
            if (c + 1 < SPEC_W) {
                if (tid < 128) {
                    int rows = (c + 1) * 64;
                    u64 acc = 0;
                    for (int r = lt; r < rows; r += 64)
                        if ((sh_keep[set][r >> 6] >> (r & 63)) & 1ull)
                            acc |= shu.scan.col[set][r];
                    for (int o = 16; o; o >>= 1) acc |= __shfl_xor_sync(0xffffffffu, acc, o);
                    if ((tid & 31) == 0 && acc) atomicOr((unsigned long long*)&sh_next[set], acc);
                }
                __syncthreads();
                if (tid < 128 && lt == 0) sh_cur[set] = sh_next[set];
                __syncthreads();
            }
        }
        if (!sh_done) { if (tid == 0) g_full = 1; }
        else emit(b, c);
    }
    gbar();

    // ---- Phase E: exact fallback (rare; grid-cooperative) ----
    full = *(volatile int*)&g_full;
    if (full) {
        for (int k = bid * TPB + tid; k < B * 65536; k += GRID * TPB) g_hist[k] = 0;
        gbar();
        for (int idx = bid * TPB + tid; idx < total; idx += GRID * TPB) {
            int b = idx / N;
            u32 u = score_map(sc2[idx].y);
            atomicAdd(&g_hist[(b << 16) + (int)(u >> 16)], 1);
        }
        gbar();
        if (bid < B && tid < 256) {
            int* h = &g_hist[bid << 16];
            int sum = 0;
            for (int k = 0; k < 256; k++) sum += h[tid * 256 + k];
            sh_part[tid] = sum;
        }
        if (bid < B) {
            __syncthreads();
            if (tid == 0) {
                int* h = &g_hist[bid << 16];
                int cum = 0, seg = 255;
                for (; seg > 0; seg--) { if (cum + sh_part[seg] >= K_PRE) break; cum += sh_part[seg]; }
                int bin = seg * 256 + 255, lo = seg * 256;
                for (;; bin--) { int cc = h[bin]; if (cum + cc >= K_PRE || bin == lo) break; cum += cc; }
                g_T16g[bid] = bin;
            }
        }
        gbar();
        for (int idx = bid * TPB + tid; idx < total; idx += GRID * TPB) {
            int b = idx / N, i = idx - b * N;
            u32 u = score_map(sc2[idx].y);
            if ((int)(u >> 16) >= g_T16g[b]) {
                int p = atomicAdd(&g_ccount[b], 1);
                if (p < CAP)
                    g_cand[b * CAP + p] = ((u64)u << 32) | (u32)(0xFFFFFFFFu - (u32)i);
            }
        }
        gbar();
        {
            int b = bid >> 5;            // 32 blocks x 512 thr per image covers CAP
            if (b < B) {
                int C = min(g_ccount[b], CAP);
                int j0 = (bid & 31) * TPB;
                if (j0 < C) {
                    int j = j0 + tid;
                    u64 my = (j < C) ? g_cand[b * CAP + j] : 0ull;
                    int rank = 0;
                    for (int c0 = 0; c0 < C; c0 += SCAP) {
                        int nt = min(SCAP, C - c0);
                        int ntp = (nt + 3) & ~3;
                        __syncthreads();
                        for (int t = tid; t < ntp; t += TPB)
                            shu.tile[t] = (t < nt) ? g_cand[b * CAP + c0 + t] : 0ull;
                        __syncthreads();
                        if (j < C) {
#pragma unroll 4
                            for (int t = 0; t < ntp; t++) rank += (shu.tile[t] > my) ? 1 : 0;
                        }
                    }
                    if (j < C && rank < K_PRE)
                        decode_write(b, rank, (u32)(my & 0xFFFFFFFFull), deltas, iminfo, anchors, N);
                }
            }
        }
        gbar();
        {
            const int per = 600;         // sum_{rt=0..11} (94-8*rt)
            int ntile = per * 2 * B;
            for (int tix = bid; tix < ntile; tix += GRID) {
                int bset = tix / per, r = tix % per;
                int rt = 0, cnt = 94;
                while (r >= cnt) { r -= cnt; rt++; cnt = 94 - 8 * rt; }
                mask_tile(bset, rt, 8 * rt + r);
            }
        }
        gbar();
        if (bid < B) scan_emit_full(bid);
        gbar();
    }

    // ---- cleanup for next graph replay ----
    if (bid == 0 && tid == 0) {
        for (int b = 0; b < MAXB; b++) { g_scount[b] = 0; g_ccount[b] = 0; }
        g_full = 0;
    }
}

extern "C" void kernel_launch(void* const* d_in, const int* in_sizes, int n_in,
                              void* d_out, int out_size) {
    const float* scores  = (const float*)d_in[0];
    const float* deltas  = (const float*)d_in[1];
    const float* iminfo  = (const float*)d_in[2];
    const float* anchors = (const float*)d_in[3];
    float* out = (float*)d_out;
    int B = in_sizes[2] / 3;
    int N = in_sizes[3] / 4;

    k_all<<<GRID, TPB>>>(out, scores, deltas, iminfo, anchors, B, N);
}

// round 17
// speedup vs baseline: 6.3586x; 1.1107x over previous
#include <cuda_runtime.h>
#include <cstdint>
#include <math.h>

typedef unsigned long long u64;
typedef unsigned int u32;

#define K_PRE 6000
#define K_SPEC 640
#define K_POST 300
#define NMS_TH 0.7f
#define CONS_TH 0.996f
#define NROW 6016
#define NWORD 94
#define WSTRIDE 96
#define MAXB 2
#define CAP 16384
#define SCAP 2048
#define SPEC_W 10
#define GRID 148
#define TPB 512

// ---------- persistent device scratch (self-cleaning across graph replays) ----------
__device__ int    g_hist[MAXB * 65536];
__device__ int    g_T16g[MAXB];
__device__ int    g_ccount[MAXB], g_scount[MAXB];   // zeroed at end of kernel
__device__ u64    g_cand[MAXB * CAP];
__device__ u64    g_scand[MAXB * SCAP];
__device__ float4 g_box[2 * MAXB * NROW];
__device__ float  g_area[2 * MAXB * NROW];
__device__ u64    g_mask[(size_t)2 * MAXB * NROW * WSTRIDE];
__device__ int    g_full;                            // reset at end of kernel
__device__ u32    g_bcnt;                            // barrier arrival count (self-resets)
__device__ volatile u32 g_bgen;                      // barrier generation (monotonic)

__device__ __forceinline__ void gbar() {
    __syncthreads();
    if (threadIdx.x == 0) {
        u32 gen = g_bgen;
        __threadfence();
        if (atomicAdd(&g_bcnt, 1) == GRID - 1) {
            g_bcnt = 0;
            __threadfence();
            g_bgen = gen + 1;
        } else {
            while (g_bgen == gen) { }
        }
        __threadfence();
    }
    __syncthreads();
}

__device__ __forceinline__ u32 score_map(float s) {
    u32 u = __float_as_uint(s);
    return (u & 0x80000000u) ? ~u : (u | 0x80000000u);
}

__device__ __forceinline__ bool iou_sup(float4 bi, float ai,
                                        float x1, float y1, float x2, float y2, float ar) {
    float xx1 = fmaxf(bi.x, x1), yy1 = fmaxf(bi.y, y1);
    float xx2 = fminf(bi.z, x2), yy2 = fminf(bi.w, y2);
    float ow = xx2 - xx1 + 1.0f, oh = yy2 - yy1 + 1.0f;
    if (!(ow > 0.0f && oh > 0.0f)) return false;
    float inter = ow * oh;
    float uni = ai + ar - inter;
    float p = NMS_TH * uni;
    bool sup = inter > p;
    if (fabsf(inter - p) <= 1e-5f * uni)     // borderline: exact IEEE decision
        sup = __fdiv_rn(inter, uni) > NMS_TH;
    return sup;
}

__device__ __forceinline__ void decode_write(int b, int rank, u32 lo,
        const float* __restrict__ deltas, const float* __restrict__ iminfo,
        const float* __restrict__ anchors, int N) {
    int i = (int)(0xFFFFFFFFu - lo);
    const float* a = anchors + (size_t)i * 4;
    float w = a[2] - a[0] + 1.0f;
    float h = a[3] - a[1] + 1.0f;
    float cx = a[0] + 0.5f * w;
    float cy = a[1] + 0.5f * h;
    const float* d = deltas + ((size_t)b * N + i) * 6;
    float Hm1 = iminfo[b * 3 + 0] - 1.0f;
    float Wm1 = iminfo[b * 3 + 1] - 1.0f;
    float eh = (float)exp((double)d[3]) * h;   // accurate exp (fast-math safe)
    float pcy = d[1] * h + cy;
    float y1 = fminf(fmaxf(pcy - 0.5f * eh, 0.f), Hm1);
    float y2 = fminf(fmaxf(pcy + 0.5f * eh, 0.f), Hm1);
    {
        float pcx = d[0] * w + cx;
        float pw = (float)exp((double)d[2]) * w;
        float x1 = fminf(fmaxf(pcx - 0.5f * pw, 0.f), Wm1);
        float x2 = fminf(fmaxf(pcx + 0.5f * pw, 0.f), Wm1);
        g_box[(b * 2 + 0) * NROW + rank] = make_float4(x1, y1, x2, y2);
        g_area[(b * 2 + 0) * NROW + rank] = (x2 - x1 + 1.0f) * (y2 - y1 + 1.0f);
    }
    {
        float pcx = d[4] * w + cx;
        float pw = (float)exp((double)d[5]) * w;
        float x1 = fminf(fmaxf(pcx - 0.5f * pw, 0.f), Wm1);
        float x2 = fminf(fmaxf(pcx + 0.5f * pw, 0.f), Wm1);
        g_box[(b * 2 + 1) * NROW + rank] = make_float4(x1, y1, x2, y2);
        g_area[(b * 2 + 1) * NROW + rank] = (x2 - x1 + 1.0f) * (y2 - y1 + 1.0f);
    }
}

union ShU {
    u64 tile[SCAP];                                                  // 16KB rank tile
    struct { u64 diag[2][SPEC_W][64]; u64 col[2][K_SPEC]; } scan;    // 10+10 KB
};

extern "C" __global__ void __launch_bounds__(TPB) k_all(
    float* __restrict__ out,
    const float* __restrict__ scores,
    const float* __restrict__ deltas,
    const float* __restrict__ iminfo,
    const float* __restrict__ anchors,
    int B, int N)
{
    __shared__ ShU   shu;
    __shared__ u64   sh_nz[2][SPEC_W];
    __shared__ float sbx1[64], sby1[64], sbx2[64], sby2[64], sbar[64];
    __shared__ u64   sh_keep[2][NWORD];
    __shared__ u64   sh_diag[2][64];                  // fallback scan only
    __shared__ u64   sh_next[2], sh_cur[2];
    __shared__ int   sh_comb, sh_done, sh_nk;
    __shared__ u64   sh_cw[NWORD];
    __shared__ int   sh_pref[NWORD];
    __shared__ int   sh_part[256];
    __shared__ int   sh_rank[TPB];

    int bid = blockIdx.x, tid = threadIdx.x;
    int total = B * N;
    const float2* sc2 = (const float2*)scores;

    // 512-row x 64-col mask tile
    auto mask_tile = [&](int bset, int rt, int cc) {
        __syncthreads();
        if (tid < 64) {
            float4 bj = g_box[bset * NROW + cc * 64 + tid];
            sbx1[tid] = bj.x; sby1[tid] = bj.y; sbx2[tid] = bj.z; sby2[tid] = bj.w;
            sbar[tid] = g_area[bset * NROW + cc * 64 + tid];
        }
        __syncthreads();
        int i = rt * TPB + tid;
        if (i < NROW) {
            float4 bi = g_box[bset * NROW + i];
            float ai = g_area[bset * NROW + i];
            u64 w = 0;
#pragma unroll 4
            for (int k = 0; k < 64; k++)
                if (cc * 64 + k > i && iou_sup(bi, ai, sbx1[k], sby1[k], sbx2[k], sby2[k], sbar[k]))
                    w |= 1ull << k;
            g_mask[((size_t)bset * NROW + i) * WSTRIDE + cc] = w;
        }
    };

    auto emit = [&](int b, int chunks) {
        float* outL = out + (size_t)b * K_POST * 5;
        float* outR = out + (size_t)(B + b) * K_POST * 5;
        for (int i2 = tid; i2 < K_POST * 5; i2 += TPB) {
            float v = (i2 % 5 == 0) ? (float)b : 0.f;
            outL[i2] = v; outR[i2] = v;
        }
        for (int w = tid; w < NWORD; w += TPB)
            sh_cw[w] = (w < chunks) ? (sh_keep[0][w] & sh_keep[1][w]) : 0ull;
        __syncthreads();
        if (tid == 0) {
            int s = 0;
            for (int w = 0; w < NWORD; w++) { sh_pref[w] = s; s += __popcll(sh_cw[w]); }
            sh_nk = s < K_POST ? s : K_POST;
        }
        __syncthreads();
        int nk = sh_nk;
        for (int w = tid; w < NWORD; w += TPB) {
            int rank = sh_pref[w];
            u64 m = sh_cw[w];
            while (m && rank < nk) {
                int k = __ffsll((long long)m) - 1; m &= m - 1;
                int r = w * 64 + k;
                float4 bl = g_box[(b * 2 + 0) * NROW + r];
                float4 br = g_box[(b * 2 + 1) * NROW + r];
                outL[rank * 5 + 1] = bl.x; outL[rank * 5 + 2] = bl.y;
                outL[rank * 5 + 3] = bl.z; outL[rank * 5 + 4] = bl.w;
                outR[rank * 5 + 1] = br.x; outR[rank * 5 + 2] = br.y;
                outR[rank * 5 + 3] = br.z; outR[rank * 5 + 4] = br.w;
                rank++;
            }
        }
        __syncthreads();
    };

    // fallback scan (global mask reads, full NWORD, always emits)
    auto scan_emit_full = [&](int b) {
        int set = (tid >> 6) & 1, lt = tid & 63;
        bool act = tid < 128;
        const u64* M = &g_mask[(size_t)(b * 2 + set) * NROW * WSTRIDE];
        if (tid == 0) { sh_comb = 0; sh_done = 0; sh_cur[0] = 0; sh_cur[1] = 0; }
        __syncthreads();
        int c = 0;
        for (; c < NWORD; c++) {
            if (act) sh_diag[set][lt] = M[(size_t)(c * 64 + lt) * WSTRIDE + c];
            __syncthreads();
            if (act && lt == 0) {
                u64 cur = sh_cur[set], keep = 0;
                int lim = min(64, K_PRE - c * 64);
                for (int k = 0; k < lim; k++)
                    if (!((cur >> k) & 1ull)) { keep |= 1ull << k; cur |= sh_diag[set][k]; }
                sh_keep[set][c] = keep;
            }
            __syncthreads();
            if (tid == 0) {
                sh_comb += __popcll(sh_keep[0][c] & sh_keep[1][c]);
                if (sh_comb >= K_POST) sh_done = 1;
            }
            if (tid < 2) sh_next[tid] = 0;
            __syncthreads();
            if (sh_done) { c++; break; }
            if (c + 1 < NWORD) {
                if (act) {
                    u64 acc = 0;
                    for (int r = lt; r < (c + 1) * 64; r += 64)
                        if ((sh_keep[set][r >> 6] >> (r & 63)) & 1ull)
                            acc |= M[(size_t)r * WSTRIDE + (c + 1)];
                    for (int o = 16; o; o >>= 1) acc |= __shfl_xor_sync(0xffffffffu, acc, o);
                    if ((tid & 31) == 0 && acc) atomicOr((unsigned long long*)&sh_next[set], acc);
                }
                __syncthreads();
                if (act && lt == 0) sh_cur[set] = sh_next[set];
                __syncthreads();
            }
        }
        emit(b, c);
    };

    // ---- Phase A: conservative compact (s >= CONS_TH), vectorized ----
    for (int b = 0; b < B; b++) {
        const float4* s4 = (const float4*)(scores + (size_t)b * N * 2);
        int n4 = N >> 1;
        for (int j = bid * TPB + tid; j < n4; j += GRID * TPB) {
            float4 v = s4[j];
            if (v.y >= CONS_TH) {
                u32 u = score_map(v.y);
                int q = atomicAdd(&g_scount[b], 1);
                if (q < SCAP)
                    g_scand[b * SCAP + q] = ((u64)u << 32) | (u32)(0xFFFFFFFFu - (u32)(2 * j));
            }
            if (v.w >= CONS_TH) {
                u32 u = score_map(v.w);
                int q = atomicAdd(&g_scount[b], 1);
                if (q < SCAP)
                    g_scand[b * SCAP + q] = ((u64)u << 32) | (u32)(0xFFFFFFFFu - (u32)(2 * j + 1));
            }
        }
        if ((N & 1) && bid == 0 && tid == 0) {
            float s = sc2[(size_t)b * N + (N - 1)].y;
            if (s >= CONS_TH) {
                u32 u = score_map(s);
                int q = atomicAdd(&g_scount[b], 1);
                if (q < SCAP)
                    g_scand[b * SCAP + q] = ((u64)u << 32) | (u32)(0xFFFFFFFFu - (u32)(N - 1));
            }
        }
    }
    gbar();

    // ---- Phase B: validate + exact rank (4-way split) + decode (16 blocks/image) ----
    if (bid == 0 && tid == 0)
        for (int b = 0; b < B; b++) {
            int C2 = g_scount[b];
            if (C2 < K_SPEC || C2 > SCAP) g_full = 1;
        }
    {
        int b = bid >> 4;
        if (b < B) {
            int C2 = min(g_scount[b], SCAP);
            int j0 = (bid & 15) * 128;
            if (j0 < C2) {
                int C2p = (C2 + 7) & ~7;
                for (int t = tid; t < C2p; t += TPB)
                    shu.tile[t] = (t < C2) ? g_scand[b * SCAP + t] : 0ull;
                __syncthreads();
                int slot = tid & 127;
                int quarter = tid >> 7;          // 0..3
                int j = j0 + slot;
                int qlen = C2p >> 2;             // divisible by 2
                u64 my = (j < C2) ? shu.tile[j] : 0ull;
                int rank = 0;
                const ulonglong2* t2 = (const ulonglong2*)(shu.tile + quarter * qlen);
                int n2 = qlen >> 1;
#pragma unroll 8
                for (int t = 0; t < n2; t++) {
                    ulonglong2 v = t2[t];
                    rank += (v.x > my) ? 1 : 0;
                    rank += (v.y > my) ? 1 : 0;
                }
                sh_rank[tid] = rank;
                __syncthreads();
                if (tid < 128 && j < C2) {
                    int r = sh_rank[tid] + sh_rank[tid + 128] + sh_rank[tid + 256] + sh_rank[tid + 384];
                    decode_write(b, r, (u32)(my & 0xFFFFFFFFull), deltas, iminfo, anchors, N);
                }
            }
        }
    }
    gbar();

    // ---- Phase C: speculative IoU mask (top SPEC_W*64 rows/cols) ----
    int full = *(volatile int*)&g_full;
    if (!full) {
        // per set: rt=0 -> cc 0..9 (10 tiles); rt=1 -> cc 8..9 (2 tiles)  => 12/set
        int ntile = 12 * 2 * B;
        for (int tix = bid; tix < ntile; tix += GRID) {
            int bset = tix / 12, r = tix % 12;
            int rt, cc;
            if (r < SPEC_W) { rt = 0; cc = r; }
            else { rt = 1; cc = 8 + (r - SPEC_W); }
            mask_tile(bset, rt, cc);
        }
    }
    gbar();

    // ---- Phase D: spec scan, streamlined (2 syncs/chunk, no per-chunk exit) ----
    full = *(volatile int*)&g_full;
    if (!full && bid < B) {
        int b = bid;
        int set = (tid >> 6) & 1;       // tid<128: chain sets; tid 128-255: prefetch sets
        int lt = tid & 63;
        const u64* Ms = &g_mask[(size_t)(b * 2 + set) * NROW * WSTRIDE];
        if (tid < 2 * SPEC_W) ((u64*)sh_nz)[tid] = 0;
        if (tid < 2) sh_next[tid] = 0;
        __syncthreads();
        for (int x = tid; x < 2 * SPEC_W * 64; x += TPB) {
            int s = (x >= SPEC_W * 64) ? 1 : 0;
            int y = x - s * SPEC_W * 64;
            int c = y >> 6;
            int r = y & 63;
            const u64* M = &g_mask[(size_t)(b * 2 + s) * NROW * WSTRIDE];
            u64 v = M[(size_t)(c * 64 + r) * WSTRIDE + c];
            shu.scan.diag[s][c][r] = v;
            if (v) atomicOr((unsigned long long*)&sh_nz[s][c], 1ull << r);
        }
        __syncthreads();
        for (int c = 0; c < SPEC_W; c++) {
            if (tid < 128) {
                if (lt == 0) {          // serial chain; reads & re-zeroes sh_next itself
                    u64 cur = sh_next[set];
                    sh_next[set] = 0;
                    u64 m = sh_nz[set][c] & ~cur;
                    while (m) {
                        int k = __ffsll((long long)m) - 1;
                        if (!((cur >> k) & 1ull)) cur |= shu.scan.diag[set][c][k];
                        m &= m - 1;
                        m &= ~cur;
                    }
                    sh_keep[set][c] = ~cur;
                }
            } else if (tid < 256 && c + 1 < SPEC_W) {   // warps 4-7: prefetch next column
                int rows = (c + 1) * 64;
                for (int r = lt; r < rows; r += 64)
                    shu.scan.col[set][r] = Ms[(size_t)r * WSTRIDE + (c + 1)];
            }
            __syncthreads();
            if (c + 1 < SPEC_W) {
                if (tid < 128) {
                    int rows = (c + 1) * 64;
                    u64 acc = 0;
                    for (int r = lt; r < rows; r += 64)
                        if ((sh_keep[set][r >> 6] >> (r & 63)) & 1ull)
                            acc |= shu.scan.col[set][r];
                    for (int o = 16; o; o >>= 1) acc |= __shfl_xor_sync(0xffffffffu, acc, o);
                    if ((tid & 31) == 0 && acc) atomicOr((unsigned long long*)&sh_next[set], acc);
                }
                __syncthreads();
            }
        }
        if (tid == 0) {
            int s = 0;
            for (int w = 0; w < SPEC_W; w++) s += __popcll(sh_keep[0][w] & sh_keep[1][w]);
            sh_done = (s >= K_POST) ? 1 : 0;
        }
        __syncthreads();
        if (!sh_done) { if (tid == 0) g_full = 1; }
        else emit(b, SPEC_W);
    }
    gbar();

    // ---- Phase E: exact fallback (rare; grid-cooperative) ----
    full = *(volatile int*)&g_full;
    if (full) {
        for (int k = bid * TPB + tid; k < B * 65536; k += GRID * TPB) g_hist[k] = 0;
        gbar();
        for (int idx = bid * TPB + tid; idx < total; idx += GRID * TPB) {
            int b = idx / N;
            u32 u = score_map(sc2[idx].y);
            atomicAdd(&g_hist[(b << 16) + (int)(u >> 16)], 1);
        }
        gbar();
        if (bid < B && tid < 256) {
            int* h = &g_hist[bid << 16];
            int sum = 0;
            for (int k = 0; k < 256; k++) sum += h[tid * 256 + k];
            sh_part[tid] = sum;
        }
        if (bid < B) {
            __syncthreads();
            if (tid == 0) {
                int* h = &g_hist[bid << 16];
                int cum = 0, seg = 255;
                for (; seg > 0; seg--) { if (cum + sh_part[seg] >= K_PRE) break; cum += sh_part[seg]; }
                int bin = seg * 256 + 255, lo = seg * 256;
                for (;; bin--) { int cc = h[bin]; if (cum + cc >= K_PRE || bin == lo) break; cum += cc; }
                g_T16g[bid] = bin;
            }
        }
        gbar();
        for (int idx = bid * TPB + tid; idx < total; idx += GRID * TPB) {
            int b = idx / N, i = idx - b * N;
            u32 u = score_map(sc2[idx].y);
            if ((int)(u >> 16) >= g_T16g[b]) {
                int p = atomicAdd(&g_ccount[b], 1);
                if (p < CAP)
                    g_cand[b * CAP + p] = ((u64)u << 32) | (u32)(0xFFFFFFFFu - (u32)i);
            }
        }
        gbar();
        {
            int b = bid >> 5;            // 32 blocks x 512 thr per image covers CAP
            if (b < B) {
                int C = min(g_ccount[b], CAP);
                int j0 = (bid & 31) * TPB;
                if (j0 < C) {
                    int j = j0 + tid;
                    u64 my = (j < C) ? g_cand[b * CAP + j] : 0ull;
                    int rank = 0;
                    for (int c0 = 0; c0 < C; c0 += SCAP) {
                        int nt = min(SCAP, C - c0);
                        int ntp = (nt + 3) & ~3;
                        __syncthreads();
                        for (int t = tid; t < ntp; t += TPB)
                            shu.tile[t] = (t < nt) ? g_cand[b * CAP + c0 + t] : 0ull;
                        __syncthreads();
                        if (j < C) {
#pragma unroll 4
                            for (int t = 0; t < ntp; t++) rank += (shu.tile[t] > my) ? 1 : 0;
                        }
                    }
                    if (j < C && rank < K_PRE)
                        decode_write(b, rank, (u32)(my & 0xFFFFFFFFull), deltas, iminfo, anchors, N);
                }
            }
        }
        gbar();
        {
            const int per = 600;         // sum_{rt=0..11} (94-8*rt)
            int ntile = per * 2 * B;
            for (int tix = bid; tix < ntile; tix += GRID) {
                int bset = tix / per, r = tix % per;
                int rt = 0, cnt = 94;
                while (r >= cnt) { r -= cnt; rt++; cnt = 94 - 8 * rt; }
                mask_tile(bset, rt, 8 * rt + r);
            }
        }
        gbar();
        if (bid < B) scan_emit_full(bid);
        gbar();
    }

    // ---- cleanup for next graph replay ----
    if (bid == 0 && tid == 0) {
        for (int b = 0; b < MAXB; b++) { g_scount[b] = 0; g_ccount[b] = 0; }
        g_full = 0;
    }
}

extern "C" void kernel_launch(void* const* d_in, const int* in_sizes, int n_in,
                              void* d_out, int out_size) {
    const float* scores  = (const float*)d_in[0];
    const float* deltas  = (const float*)d_in[1];
    const float* iminfo  = (const float*)d_in[2];
    const float* anchors = (const float*)d_in[3];
    float* out = (float*)d_out;
    int B = in_sizes[2] / 3;
    int N = in_sizes[3] / 4;

    k_all<<<GRID, TPB>>>(out, scores, deltas, iminfo, anchors, B, N);
}